// round 11
// baseline (speedup 1.0000x reference)
#include <cuda_runtime.h>
#include <cuda_bf16.h>
#include <math.h>
#include <stdint.h>

#define Bb 2
#define Nn 2048
#define Cc 1024
#define Hh 16
#define Dd 64
#define Mtot (Bb*Nn)     /* 4096 */
#define K3  (3*Cc)       /* 3072 */
#define SL2E 0.1803368801111244f   /* 0.125 * log2(e) */

// ---------------- scratch ----------------------------------------------------
__device__ __align__(16) uint16_t g_wqh[(size_t)K3*Cc], g_wql[(size_t)K3*Cc]; // WqkvT [n][k]
__device__ __align__(16) uint16_t g_woh[(size_t)Cc*Cc], g_wol[(size_t)Cc*Cc]; // WoutT [n][k]
__device__ __align__(16) uint16_t g_xh[(size_t)Mtot*Cc], g_xl[(size_t)Mtot*Cc]; // x split
__device__ __align__(16) uint16_t g_oh[(size_t)Mtot*Cc], g_ol[(size_t)Mtot*Cc]; // attn-out split
__device__ float g_q[(size_t)Bb*Hh*Nn*Dd];   // [bh][pos][d]
__device__ float g_k[(size_t)Bb*Hh*Nn*Dd];
__device__ float g_v[(size_t)Bb*Hh*Nn*Dd];
__device__ float g_o[(size_t)Mtot*Cc];       // [b*Nn+q][h*64+d]
__device__ float g_cos[Nn*32], g_sin[Nn*32];

// ---------------- helpers ----------------------------------------------------
__device__ __forceinline__ uint32_t smem_u32(const void* p) {
    uint32_t a;
    asm("{ .reg .u64 t; cvta.to.shared.u64 t, %1; cvt.u32.u64 %0, t; }" : "=r"(a) : "l"(p));
    return a;
}
__device__ __forceinline__ void cpa16(uint32_t s, const void* g) {
    asm volatile("cp.async.cg.shared.global [%0], [%1], 16;" :: "r"(s), "l"(g) : "memory");
}
#define CP_COMMIT() asm volatile("cp.async.commit_group;" ::: "memory")
#define CP_WAIT0()  asm volatile("cp.async.wait_group 0;" ::: "memory")
#define CP_WAIT1()  asm volatile("cp.async.wait_group 1;" ::: "memory")

__device__ __forceinline__ void ldsm4(uint32_t* r, uint32_t addr) {
    asm volatile("ldmatrix.sync.aligned.m8n8.x4.shared.b16 {%0,%1,%2,%3}, [%4];"
        : "=r"(r[0]), "=r"(r[1]), "=r"(r[2]), "=r"(r[3]) : "r"(addr));
}
__device__ __forceinline__ void mma_bf16(float* c, const uint32_t* a, const uint32_t* b) {
    asm volatile("mma.sync.aligned.m16n8k16.row.col.f32.bf16.bf16.f32 "
        "{%0,%1,%2,%3}, {%4,%5,%6,%7}, {%8,%9}, {%0,%1,%2,%3};"
        : "+f"(c[0]), "+f"(c[1]), "+f"(c[2]), "+f"(c[3])
        : "r"(a[0]), "r"(a[1]), "r"(a[2]), "r"(a[3]), "r"(b[0]), "r"(b[1]));
}
__device__ __forceinline__ void fsplit(float x, uint16_t& h, uint16_t& lo) {
    __nv_bfloat16 hb = __float2bfloat16_rn(x);
    float r = x - __bfloat162float(hb);
    __nv_bfloat16 lb = __float2bfloat16_rn(r);
    h  = *(uint16_t*)&hb;
    lo = *(uint16_t*)&lb;
}
__device__ __forceinline__ float ex2(float x) {
    float y;
    asm("ex2.approx.ftz.f32 %0, %1;" : "=f"(y) : "f"(x));
    return y;
}

// ---------------- init kernels -----------------------------------------------
__global__ void rope_init_kernel() {
    int idx = blockIdx.x * blockDim.x + threadIdx.x;
    if (idx >= Nn * 32) return;
    int n = idx >> 5, i = idx & 31;
    float invf = powf(10000.0f, -(float)i / 32.0f);
    float f = (float)n * invf;
    g_cos[idx] = cosf(f);
    g_sin[idx] = sinf(f);
}

// Split a [Mtot*Cc] fp32 array to bf16 h/l.  which=0: src=xp -> g_xh/g_xl;
// which=1: src=g_o -> g_oh/g_ol.  Device symbols referenced in DEVICE code only
// (GB300/ATS trap: host-passed __device__ symbol silently writes host shadow).
__global__ __launch_bounds__(256) void split_kernel(const float* __restrict__ xp, int which) {
    const float* src = which ? g_o : xp;
    uint16_t* __restrict__ dh = which ? g_oh : g_xh;
    uint16_t* __restrict__ dl = which ? g_ol : g_xl;
    size_t i = ((size_t)blockIdx.x * 256 + threadIdx.x) * 4;
    float4 v = *(const float4*)(src + i);
    uint16_t h0,l0,h1,l1,h2,l2,h3,l3;
    fsplit(v.x, h0, l0); fsplit(v.y, h1, l1);
    fsplit(v.z, h2, l2); fsplit(v.w, h3, l3);
    uint2 hp = make_uint2((uint32_t)h0 | ((uint32_t)h1 << 16),
                          (uint32_t)h2 | ((uint32_t)h3 << 16));
    uint2 lp = make_uint2((uint32_t)l0 | ((uint32_t)l1 << 16),
                          (uint32_t)l2 | ((uint32_t)l3 << 16));
    *(uint2*)(dh + i) = hp;
    *(uint2*)(dl + i) = lp;
}

// W [R][C] -> T [C][R] (split hi/lo), device-selected destinations.
__global__ void transpose_split_kernel(const float* __restrict__ W,
                                       int R, int C, int which) {
    uint16_t* __restrict__ Th = which ? g_woh : g_wqh;
    uint16_t* __restrict__ Tl = which ? g_wol : g_wql;
    __shared__ float tile[32][33];
    int bx = blockIdx.x * 32, by = blockIdx.y * 32;
    int tx = threadIdx.x, ty = threadIdx.y;
#pragma unroll
    for (int i = 0; i < 4; i++)
        tile[ty + 8*i][tx] = W[(size_t)(by + ty + 8*i) * C + bx + tx];
    __syncthreads();
#pragma unroll
    for (int i = 0; i < 4; i++) {
        float v = tile[tx][ty + 8*i];
        uint16_t h, l;
        fsplit(v, h, l);
        size_t o = (size_t)(bx + ty + 8*i) * R + by + tx;
        Th[o] = h; Tl[o] = l;
    }
}

// ====== bf16x3 GEMM core: ALL operands pre-split, 3-stage cp.async ==========
// 128x128 tile, BK=32, 256 threads (warps 2x4, warp tile 64x32), ldmatrix.
// Stage (40960 B): Ah 0 | Al 10240 | Bh 20480 | Bl 30720; row stride 80 B.
#define GEMM_SMEM (3*40960)
#define GP 40

__device__ __forceinline__ void gemm_core3(
    const uint16_t* __restrict__ Ah, const uint16_t* __restrict__ Al,
    const uint16_t* __restrict__ Bh, const uint16_t* __restrict__ Bl,
    int bm, int bn, char* sm, float acc[4][4][4])
{
    int tid = threadIdx.x, l = tid & 31, w = tid >> 5;
    int wm = (w >> 2) * 64, wn = (w & 3) * 32;
    uint32_t sb0 = smem_u32(sm);

#pragma unroll
    for (int mf = 0; mf < 4; mf++)
#pragma unroll
        for (int nf = 0; nf < 4; nf++)
#pragma unroll
            for (int i = 0; i < 4; i++) acc[mf][nf][i] = 0.0f;

    auto issue = [&](int st, int kt) {
        uint32_t s0 = sb0 + st * 40960;
#pragma unroll
        for (int i = 0; i < 2; i++) {
            int ch = tid + 256 * i;
            int r = ch >> 2, g = ch & 3;           // row, 16B group
            uint32_t d = s0 + r * 80 + g * 16;
            size_t offa = (size_t)(bm + r) * Cc + kt * 32 + g * 8;
            size_t offb = (size_t)(bn + r) * Cc + kt * 32 + g * 8;
            cpa16(d,          Ah + offa);
            cpa16(d + 10240,  Al + offa);
            cpa16(d + 20480,  Bh + offb);
            cpa16(d + 30720,  Bl + offb);
        }
    };

    issue(0, 0); CP_COMMIT();
    issue(1, 1); CP_COMMIT();

    int st = 0;
    for (int kt = 0; kt < 32; kt++) {
        if (kt + 1 < 32) CP_WAIT1(); else CP_WAIT0();
        __syncthreads();
        if (kt + 2 < 32) {
            int st2 = st + 2; if (st2 >= 3) st2 -= 3;
            issue(st2, kt + 2); CP_COMMIT();
        }

        uint32_t sb = sb0 + st * 40960;
#pragma unroll
        for (int ks = 0; ks < 2; ks++) {
            int k0 = ks * 16;
            uint32_t ah[4][4], al[4][4];
            uint32_t arow = (uint32_t)(wm + (l & 15));
            uint32_t acol = (uint32_t)(k0 + (l >> 4) * 8);
#pragma unroll
            for (int mf = 0; mf < 4; mf++) {
                uint32_t off = ((arow + mf * 16) * GP + acol) * 2;
                ldsm4(ah[mf], sb + off);
                ldsm4(al[mf], sb + 10240 + off);
            }
            uint32_t bh2[4][2], bl2[4][2];
            uint32_t brow = (uint32_t)(wn + (l >> 4) * 8 + (l & 7));
            uint32_t bcol = (uint32_t)(k0 + ((l >> 3) & 1) * 8);
#pragma unroll
            for (int p = 0; p < 2; p++) {
                uint32_t off = ((brow + p * 16) * GP + bcol) * 2;
                uint32_t tb[4];
                ldsm4(tb, sb + 20480 + off);
                bh2[2*p][0] = tb[0]; bh2[2*p][1] = tb[1];
                bh2[2*p+1][0] = tb[2]; bh2[2*p+1][1] = tb[3];
                ldsm4(tb, sb + 30720 + off);
                bl2[2*p][0] = tb[0]; bl2[2*p][1] = tb[1];
                bl2[2*p+1][0] = tb[2]; bl2[2*p+1][1] = tb[3];
            }
#pragma unroll
            for (int nf = 0; nf < 4; nf++)
#pragma unroll
                for (int mf = 0; mf < 4; mf++) {
                    mma_bf16(acc[mf][nf], ah[mf], bh2[nf]);
                    mma_bf16(acc[mf][nf], al[mf], bh2[nf]);
                    mma_bf16(acc[mf][nf], ah[mf], bl2[nf]);
                }
        }
        __syncthreads();     // all reads of stage st done before it is refilled
        if (++st >= 3) st = 0;
    }
}

// ---------------- GEMM1: qkv + RoPE epilogue ---------------------------------
__global__ __launch_bounds__(256) void qkv_mma_gemm(void) {
    extern __shared__ char sm[];
    int bm = blockIdx.y * 128, bn = blockIdx.x * 128;
    float acc[4][4][4];
    gemm_core3(g_xh, g_xl, g_wqh, g_wql, bm, bn, sm, acc);

    int tid = threadIdx.x, l = tid & 31, w = tid >> 5;
    int wm = (w >> 2) * 64, wn = (w & 3) * 32;

#pragma unroll
    for (int mf = 0; mf < 4; mf++) {
#pragma unroll
        for (int half = 0; half < 2; half++) {
            int row = bm + wm + mf * 16 + (l >> 2) + half * 8;
            int b = row >> 11;
            int tok = row & (Nn - 1);
#pragma unroll
            for (int nf = 0; nf < 4; nf++) {
                int col = bn + wn + nf * 8 + (l & 3) * 2;   // even
                float y0 = acc[mf][nf][half * 2 + 0];
                float y1 = acc[mf][nf][half * 2 + 1];
                int region = col >> 10;
                int cc = col & 1023;
                int h = cc >> 6;
                int dd = cc & 63;
                size_t base = ((size_t)(b * Hh + h) * Nn + tok) * Dd;
                if (region == 2) {
                    *(float2*)(g_v + base + dd) = make_float2(y0, y1);
                } else {
                    float* dst = region ? g_k : g_q;
                    int i1 = dd >> 1;
                    float cs = g_cos[tok * 32 + i1];
                    float sn = g_sin[tok * 32 + i1];
                    dst[base + i1]      = y0 * cs - y1 * sn;
                    dst[base + i1 + 32] = y0 * sn + y1 * cs;
                }
            }
        }
    }
}

// ---------------- GEMM3: out = O @ WoutT + bias ------------------------------
__global__ __launch_bounds__(256) void out_mma_gemm(const float* __restrict__ bias,
                                                    float* __restrict__ out) {
    extern __shared__ char sm[];
    int bm = blockIdx.y * 128, bn = blockIdx.x * 128;
    float acc[4][4][4];
    gemm_core3(g_oh, g_ol, g_woh, g_wol, bm, bn, sm, acc);

    int tid = threadIdx.x, l = tid & 31, w = tid >> 5;
    int wm = (w >> 2) * 64, wn = (w & 3) * 32;

#pragma unroll
    for (int mf = 0; mf < 4; mf++) {
#pragma unroll
        for (int half = 0; half < 2; half++) {
            int row = bm + wm + mf * 16 + (l >> 2) + half * 8;
#pragma unroll
            for (int nf = 0; nf < 4; nf++) {
                int col = bn + wn + nf * 8 + (l & 3) * 2;
                float y0 = acc[mf][nf][half * 2 + 0] + bias[col];
                float y1 = acc[mf][nf][half * 2 + 1] + bias[col + 1];
                *(float2*)(out + (size_t)row * Cc + col) = make_float2(y0, y1);
            }
        }
    }
}

// ===================== Flash attention (R7/R10 verbatim, proven) =============
#define AP 72
#define AT_SMEM 73728

__global__ __launch_bounds__(256) void flash_mma_kernel() {
    extern __shared__ char sm[];
    uint16_t* sQh = (uint16_t*)sm;
    uint16_t* sQl = (uint16_t*)(sm + 18432);
    uint16_t* sKh = (uint16_t*)(sm + 36864);
    uint16_t* sKl = (uint16_t*)(sm + 46080);
    uint16_t* sVh = (uint16_t*)(sm + 55296);
    uint16_t* sVl = (uint16_t*)(sm + 64512);

    int tid = threadIdx.x, l = tid & 31, w = tid >> 5;
    int wm = w * 16;
    int bh = blockIdx.y;
    int qb = blockIdx.x;
    int b = bh >> 4, h = bh & 15;

    const float* Qp = g_q + ((size_t)bh * Nn + qb * 128) * Dd;
#pragma unroll
    for (int i = 0; i < 8; i++) {
        int idx = tid + 256 * i;
        int r = idx >> 4, c4 = (idx & 15) * 4;
        float4 v = *(const float4*)(Qp + (size_t)r * Dd + c4);
        uint16_t h0,l0,h1,l1,h2,l2,h3,l3;
        fsplit(v.x, h0, l0); fsplit(v.y, h1, l1);
        fsplit(v.z, h2, l2); fsplit(v.w, h3, l3);
        uint32_t* ph = (uint32_t*)&sQh[r * AP + c4];
        uint32_t* pl = (uint32_t*)&sQl[r * AP + c4];
        ph[0] = (uint32_t)h0 | ((uint32_t)h1 << 16);
        ph[1] = (uint32_t)h2 | ((uint32_t)h3 << 16);
        pl[0] = (uint32_t)l0 | ((uint32_t)l1 << 16);
        pl[1] = (uint32_t)l2 | ((uint32_t)l3 << 16);
    }

    float O[8][4];
#pragma unroll
    for (int nf = 0; nf < 8; nf++)
#pragma unroll
        for (int i = 0; i < 4; i++) O[nf][i] = 0.0f;
    float mrow[2] = {-1e30f, -1e30f};
    float lsum[2] = {0.0f, 0.0f};

    const float* Kp = g_k + (size_t)bh * Nn * Dd;
    const float* Vp = g_v + (size_t)bh * Nn * Dd;

    const int ntiles = 2 * qb + 2;
    for (int t = 0; t < ntiles; t++) {
        float4 kv4[4], vv4[4];
#pragma unroll
        for (int i = 0; i < 4; i++) {
            int idx = tid + 256 * i;
            int r = idx >> 4, c4 = (idx & 15) * 4;
            kv4[i] = *(const float4*)(Kp + (size_t)(t * 64 + r) * Dd + c4);
            vv4[i] = *(const float4*)(Vp + (size_t)(t * 64 + r) * Dd + c4);
        }
        __syncthreads();
#pragma unroll
        for (int i = 0; i < 4; i++) {
            int idx = tid + 256 * i;
            int r = idx >> 4, c4 = (idx & 15) * 4;
            uint16_t h0,l0,h1,l1,h2,l2,h3,l3;
            fsplit(kv4[i].x, h0, l0); fsplit(kv4[i].y, h1, l1);
            fsplit(kv4[i].z, h2, l2); fsplit(kv4[i].w, h3, l3);
            uint32_t* ph = (uint32_t*)&sKh[r * AP + c4];
            uint32_t* pl = (uint32_t*)&sKl[r * AP + c4];
            ph[0] = (uint32_t)h0 | ((uint32_t)h1 << 16);
            ph[1] = (uint32_t)h2 | ((uint32_t)h3 << 16);
            pl[0] = (uint32_t)l0 | ((uint32_t)l1 << 16);
            pl[1] = (uint32_t)l2 | ((uint32_t)l3 << 16);
            float vs[4] = {vv4[i].x, vv4[i].y, vv4[i].z, vv4[i].w};
#pragma unroll
            for (int j = 0; j < 4; j++) {
                uint16_t hh, ll;
                fsplit(vs[j], hh, ll);
                sVh[(c4 + j) * AP + r] = hh;
                sVl[(c4 + j) * AP + r] = ll;
            }
        }
        __syncthreads();

        float S[8][4];
#pragma unroll
        for (int nf = 0; nf < 8; nf++)
#pragma unroll
            for (int i = 0; i < 4; i++) S[nf][i] = 0.0f;

#pragma unroll
        for (int ks = 0; ks < 4; ks++) {
            int kc = ks * 16 + (l & 3) * 2;
            int r = wm + (l >> 2);
            uint32_t qh[4], ql[4];
            qh[0] = *(const uint32_t*)&sQh[(r    ) * AP + kc];
            qh[1] = *(const uint32_t*)&sQh[(r + 8) * AP + kc];
            qh[2] = *(const uint32_t*)&sQh[(r    ) * AP + kc + 8];
            qh[3] = *(const uint32_t*)&sQh[(r + 8) * AP + kc + 8];
            ql[0] = *(const uint32_t*)&sQl[(r    ) * AP + kc];
            ql[1] = *(const uint32_t*)&sQl[(r + 8) * AP + kc];
            ql[2] = *(const uint32_t*)&sQl[(r    ) * AP + kc + 8];
            ql[3] = *(const uint32_t*)&sQl[(r + 8) * AP + kc + 8];
#pragma unroll
            for (int nf = 0; nf < 8; nf++) {
                int n = nf * 8 + (l >> 2);
                uint32_t kh2[2], kl2[2];
                kh2[0] = *(const uint32_t*)&sKh[n * AP + kc];
                kh2[1] = *(const uint32_t*)&sKh[n * AP + kc + 8];
                kl2[0] = *(const uint32_t*)&sKl[n * AP + kc];
                kl2[1] = *(const uint32_t*)&sKl[n * AP + kc + 8];
                mma_bf16(S[nf], qh, kh2);
                mma_bf16(S[nf], ql, kh2);
                mma_bf16(S[nf], qh, kl2);
            }
        }

        bool domask = (t >= 2 * qb);
#pragma unroll
        for (int nf = 0; nf < 8; nf++)
#pragma unroll
            for (int idx = 0; idx < 4; idx++) {
                float v = S[nf][idx] * SL2E;
                if (domask) {
                    int h2 = idx >> 1, ci = idx & 1;
                    int qg = qb * 128 + wm + (l >> 2) + h2 * 8;
                    int kg = t * 64 + nf * 8 + (l & 3) * 2 + ci;
                    if (kg > qg) v = -1e30f;
                }
                S[nf][idx] = v;
            }

#pragma unroll
        for (int h2 = 0; h2 < 2; h2++) {
            float mx = -1e30f;
#pragma unroll
            for (int nf = 0; nf < 8; nf++)
                mx = fmaxf(mx, fmaxf(S[nf][h2*2], S[nf][h2*2+1]));
            mx = fmaxf(mx, __shfl_xor_sync(0xffffffffu, mx, 1));
            mx = fmaxf(mx, __shfl_xor_sync(0xffffffffu, mx, 2));
            float mnew = fmaxf(mrow[h2], mx);
            float scl = ex2(mrow[h2] - mnew);
            float sum = 0.0f;
#pragma unroll
            for (int nf = 0; nf < 8; nf++) {
                float p0 = ex2(S[nf][h2*2]   - mnew);
                float p1 = ex2(S[nf][h2*2+1] - mnew);
                S[nf][h2*2]   = p0;
                S[nf][h2*2+1] = p1;
                sum += p0 + p1;
            }
            sum += __shfl_xor_sync(0xffffffffu, sum, 1);
            sum += __shfl_xor_sync(0xffffffffu, sum, 2);
            lsum[h2] = lsum[h2] * scl + sum;
            mrow[h2] = mnew;
#pragma unroll
            for (int nf = 0; nf < 8; nf++) {
                O[nf][h2*2]   *= scl;
                O[nf][h2*2+1] *= scl;
            }
        }

#pragma unroll
        for (int ks = 0; ks < 4; ks++) {
            uint32_t ph[4], pl[4];
#pragma unroll
            for (int half = 0; half < 2; half++) {
#pragma unroll
                for (int rr = 0; rr < 2; rr++) {
                    float v0 = S[2*ks + half][rr*2];
                    float v1 = S[2*ks + half][rr*2 + 1];
                    uint16_t a0, b0, a1, b1;
                    fsplit(v0, a0, b0);
                    fsplit(v1, a1, b1);
                    ph[half*2 + rr] = (uint32_t)a0 | ((uint32_t)a1 << 16);
                    pl[half*2 + rr] = (uint32_t)b0 | ((uint32_t)b1 << 16);
                }
            }
            int kc = ks * 16 + (l & 3) * 2;
#pragma unroll
            for (int nf = 0; nf < 8; nf++) {
                int n = nf * 8 + (l >> 2);
                uint32_t vh2[2], vl2[2];
                vh2[0] = *(const uint32_t*)&sVh[n * AP + kc];
                vh2[1] = *(const uint32_t*)&sVh[n * AP + kc + 8];
                vl2[0] = *(const uint32_t*)&sVl[n * AP + kc];
                vl2[1] = *(const uint32_t*)&sVl[n * AP + kc + 8];
                mma_bf16(O[nf], ph, vh2);
                mma_bf16(O[nf], pl, vh2);
                mma_bf16(O[nf], ph, vl2);
            }
        }
    }

    float inv[2] = {1.0f / lsum[0], 1.0f / lsum[1]};
#pragma unroll
    for (int nf = 0; nf < 8; nf++)
#pragma unroll
        for (int h2 = 0; h2 < 2; h2++) {
            int q = qb * 128 + wm + (l >> 2) + h2 * 8;
            int col = h * 64 + nf * 8 + (l & 3) * 2;
            size_t o = (size_t)(b * Nn + q) * Cc + col;
            *(float2*)(g_o + o) = make_float2(O[nf][h2*2] * inv[h2],
                                              O[nf][h2*2+1] * inv[h2]);
        }
}

// ---------------- launch -----------------------------------------------------
extern "C" void kernel_launch(void* const* d_in, const int* in_sizes, int n_in,
                              void* d_out, int out_size)
{
    (void)in_sizes; (void)n_in; (void)out_size;
    const float* x    = (const float*)d_in[0];
    const float* Wqkv = (const float*)d_in[1];
    const float* Wout = (const float*)d_in[2];
    const float* bout = (const float*)d_in[3];
    float* out = (float*)d_out;

    cudaFuncSetAttribute(qkv_mma_gemm, cudaFuncAttributeMaxDynamicSharedMemorySize, GEMM_SMEM);
    cudaFuncSetAttribute(out_mma_gemm, cudaFuncAttributeMaxDynamicSharedMemorySize, GEMM_SMEM);
    cudaFuncSetAttribute(flash_mma_kernel, cudaFuncAttributeMaxDynamicSharedMemorySize, AT_SMEM);

    rope_init_kernel<<<(Nn * 32 + 255) / 256, 256>>>();
    split_kernel<<<(Mtot * Cc / 4) / 256, 256>>>(x, 0);
    transpose_split_kernel<<<dim3(K3 / 32, Cc / 32), dim3(32, 8)>>>(Wqkv, Cc, K3, 0);
    transpose_split_kernel<<<dim3(Cc / 32, Cc / 32), dim3(32, 8)>>>(Wout, Cc, Cc, 1);
    qkv_mma_gemm<<<dim3(K3 / 128, Mtot / 128), 256, GEMM_SMEM>>>();
    flash_mma_kernel<<<dim3(Nn / 128, Bb * Hh), 256, AT_SMEM>>>();
    split_kernel<<<(Mtot * Cc / 4) / 256, 256>>>(nullptr, 1);
    out_mma_gemm<<<dim3(Cc / 128, Mtot / 128), 256, GEMM_SMEM>>>(bout, out);
}

// round 12
// speedup vs baseline: 1.0162x; 1.0162x over previous
#include <cuda_runtime.h>
#include <cuda_bf16.h>
#include <math.h>
#include <stdint.h>

#define Bb 2
#define Nn 2048
#define Cc 1024
#define Hh 16
#define Dd 64
#define Mtot (Bb*Nn)     /* 4096 */
#define K3  (3*Cc)       /* 3072 */
#define SL2E 0.1803368801111244f   /* 0.125 * log2(e) */

// ---------------- scratch ----------------------------------------------------
__device__ __align__(16) uint16_t g_wqh[(size_t)K3*Cc], g_wql[(size_t)K3*Cc]; // WqkvT [n][k]
__device__ __align__(16) uint16_t g_woh[(size_t)Cc*Cc], g_wol[(size_t)Cc*Cc]; // WoutT [n][k]
__device__ __align__(16) uint16_t g_xh[(size_t)Mtot*Cc], g_xl[(size_t)Mtot*Cc]; // x split
__device__ __align__(16) uint16_t g_qh[(size_t)Bb*Hh*Nn*Dd], g_ql[(size_t)Bb*Hh*Nn*Dd]; // [bh][pos][d]
__device__ __align__(16) uint16_t g_kh[(size_t)Bb*Hh*Nn*Dd], g_kl[(size_t)Bb*Hh*Nn*Dd]; // [bh][pos][d]
__device__ __align__(16) uint16_t g_vh[(size_t)Bb*Hh*Nn*Dd], g_vl[(size_t)Bb*Hh*Nn*Dd]; // [bh][d][pos]
__device__ __align__(16) uint16_t g_oh[(size_t)Mtot*Cc], g_ol[(size_t)Mtot*Cc]; // attn out [m][c]
__device__ float g_cos[Nn*32], g_sin[Nn*32];

// ---------------- helpers ----------------------------------------------------
__device__ __forceinline__ uint32_t smem_u32(const void* p) {
    uint32_t a;
    asm("{ .reg .u64 t; cvta.to.shared.u64 t, %1; cvt.u32.u64 %0, t; }" : "=r"(a) : "l"(p));
    return a;
}
__device__ __forceinline__ void cpa16(uint32_t s, const void* g) {
    asm volatile("cp.async.cg.shared.global [%0], [%1], 16;" :: "r"(s), "l"(g) : "memory");
}
#define CP_COMMIT() asm volatile("cp.async.commit_group;" ::: "memory")
#define CP_WAIT0()  asm volatile("cp.async.wait_group 0;" ::: "memory")
#define CP_WAIT1()  asm volatile("cp.async.wait_group 1;" ::: "memory")

__device__ __forceinline__ void ldsm4(uint32_t* r, uint32_t addr) {
    asm volatile("ldmatrix.sync.aligned.m8n8.x4.shared.b16 {%0,%1,%2,%3}, [%4];"
        : "=r"(r[0]), "=r"(r[1]), "=r"(r[2]), "=r"(r[3]) : "r"(addr));
}
__device__ __forceinline__ void mma_bf16(float* c, const uint32_t* a, const uint32_t* b) {
    asm volatile("mma.sync.aligned.m16n8k16.row.col.f32.bf16.bf16.f32 "
        "{%0,%1,%2,%3}, {%4,%5,%6,%7}, {%8,%9}, {%0,%1,%2,%3};"
        : "+f"(c[0]), "+f"(c[1]), "+f"(c[2]), "+f"(c[3])
        : "r"(a[0]), "r"(a[1]), "r"(a[2]), "r"(a[3]), "r"(b[0]), "r"(b[1]));
}
__device__ __forceinline__ void fsplit(float x, uint16_t& h, uint16_t& lo) {
    __nv_bfloat16 hb = __float2bfloat16_rn(x);
    float r = x - __bfloat162float(hb);
    __nv_bfloat16 lb = __float2bfloat16_rn(r);
    h  = *(uint16_t*)&hb;
    lo = *(uint16_t*)&lb;
}
__device__ __forceinline__ float ex2(float x) {
    float y;
    asm("ex2.approx.ftz.f32 %0, %1;" : "=f"(y) : "f"(x));
    return y;
}

// ---------------- init kernels -----------------------------------------------
__global__ void rope_init_kernel() {
    int idx = blockIdx.x * blockDim.x + threadIdx.x;
    if (idx >= Nn * 32) return;
    int n = idx >> 5, i = idx & 31;
    float invf = powf(10000.0f, -(float)i / 32.0f);
    float f = (float)n * invf;
    g_cos[idx] = cosf(f);
    g_sin[idx] = sinf(f);
}

// Split x -> g_xh/g_xl (device-symbol destinations referenced in device code).
__global__ __launch_bounds__(256) void split_x_kernel(const float* __restrict__ xp) {
    size_t i = ((size_t)blockIdx.x * 256 + threadIdx.x) * 4;
    float4 v = *(const float4*)(xp + i);
    uint16_t h0,l0,h1,l1,h2,l2,h3,l3;
    fsplit(v.x, h0, l0); fsplit(v.y, h1, l1);
    fsplit(v.z, h2, l2); fsplit(v.w, h3, l3);
    *(uint2*)(g_xh + i) = make_uint2((uint32_t)h0 | ((uint32_t)h1 << 16),
                                     (uint32_t)h2 | ((uint32_t)h3 << 16));
    *(uint2*)(g_xl + i) = make_uint2((uint32_t)l0 | ((uint32_t)l1 << 16),
                                     (uint32_t)l2 | ((uint32_t)l3 << 16));
}

// W [R][C] -> T [C][R] (split hi/lo), device-selected destinations.
__global__ void transpose_split_kernel(const float* __restrict__ W,
                                       int R, int C, int which) {
    uint16_t* __restrict__ Th = which ? g_woh : g_wqh;
    uint16_t* __restrict__ Tl = which ? g_wol : g_wql;
    __shared__ float tile[32][33];
    int bx = blockIdx.x * 32, by = blockIdx.y * 32;
    int tx = threadIdx.x, ty = threadIdx.y;
#pragma unroll
    for (int i = 0; i < 4; i++)
        tile[ty + 8*i][tx] = W[(size_t)(by + ty + 8*i) * C + bx + tx];
    __syncthreads();
#pragma unroll
    for (int i = 0; i < 4; i++) {
        float v = tile[tx][ty + 8*i];
        uint16_t h, l;
        fsplit(v, h, l);
        size_t o = (size_t)(bx + ty + 8*i) * R + by + tx;
        Th[o] = h; Tl[o] = l;
    }
}

// ====== bf16x3 GEMM core (R11): all operands pre-split, 3-stage cp.async =====
#define GEMM_SMEM (3*40960)
#define GP 40

__device__ __forceinline__ void gemm_core3(
    const uint16_t* __restrict__ Ah, const uint16_t* __restrict__ Al,
    const uint16_t* __restrict__ Bh, const uint16_t* __restrict__ Bl,
    int bm, int bn, char* sm, float acc[4][4][4])
{
    int tid = threadIdx.x, l = tid & 31, w = tid >> 5;
    int wm = (w >> 2) * 64, wn = (w & 3) * 32;
    uint32_t sb0 = smem_u32(sm);

#pragma unroll
    for (int mf = 0; mf < 4; mf++)
#pragma unroll
        for (int nf = 0; nf < 4; nf++)
#pragma unroll
            for (int i = 0; i < 4; i++) acc[mf][nf][i] = 0.0f;

    auto issue = [&](int st, int kt) {
        uint32_t s0 = sb0 + st * 40960;
#pragma unroll
        for (int i = 0; i < 2; i++) {
            int ch = tid + 256 * i;
            int r = ch >> 2, g = ch & 3;
            uint32_t d = s0 + r * 80 + g * 16;
            size_t offa = (size_t)(bm + r) * Cc + kt * 32 + g * 8;
            size_t offb = (size_t)(bn + r) * Cc + kt * 32 + g * 8;
            cpa16(d,          Ah + offa);
            cpa16(d + 10240,  Al + offa);
            cpa16(d + 20480,  Bh + offb);
            cpa16(d + 30720,  Bl + offb);
        }
    };

    issue(0, 0); CP_COMMIT();
    issue(1, 1); CP_COMMIT();

    int st = 0;
    for (int kt = 0; kt < 32; kt++) {
        if (kt + 1 < 32) CP_WAIT1(); else CP_WAIT0();
        __syncthreads();
        if (kt + 2 < 32) {
            int st2 = st + 2; if (st2 >= 3) st2 -= 3;
            issue(st2, kt + 2); CP_COMMIT();
        }

        uint32_t sb = sb0 + st * 40960;
#pragma unroll
        for (int ks = 0; ks < 2; ks++) {
            int k0 = ks * 16;
            uint32_t ah[4][4], al[4][4];
            uint32_t arow = (uint32_t)(wm + (l & 15));
            uint32_t acol = (uint32_t)(k0 + (l >> 4) * 8);
#pragma unroll
            for (int mf = 0; mf < 4; mf++) {
                uint32_t off = ((arow + mf * 16) * GP + acol) * 2;
                ldsm4(ah[mf], sb + off);
                ldsm4(al[mf], sb + 10240 + off);
            }
            uint32_t bh2[4][2], bl2[4][2];
            uint32_t brow = (uint32_t)(wn + (l >> 4) * 8 + (l & 7));
            uint32_t bcol = (uint32_t)(k0 + ((l >> 3) & 1) * 8);
#pragma unroll
            for (int p = 0; p < 2; p++) {
                uint32_t off = ((brow + p * 16) * GP + bcol) * 2;
                uint32_t tb[4];
                ldsm4(tb, sb + 20480 + off);
                bh2[2*p][0] = tb[0]; bh2[2*p][1] = tb[1];
                bh2[2*p+1][0] = tb[2]; bh2[2*p+1][1] = tb[3];
                ldsm4(tb, sb + 30720 + off);
                bl2[2*p][0] = tb[0]; bl2[2*p][1] = tb[1];
                bl2[2*p+1][0] = tb[2]; bl2[2*p+1][1] = tb[3];
            }
#pragma unroll
            for (int nf = 0; nf < 4; nf++)
#pragma unroll
                for (int mf = 0; mf < 4; mf++) {
                    mma_bf16(acc[mf][nf], ah[mf], bh2[nf]);
                    mma_bf16(acc[mf][nf], al[mf], bh2[nf]);
                    mma_bf16(acc[mf][nf], ah[mf], bl2[nf]);
                }
        }
        __syncthreads();
        if (++st >= 3) st = 0;
    }
}

// ---------------- GEMM1: qkv + RoPE epilogue, writes pre-split Q/K/V ---------
// Q/K: bf16 h/l [bh][pos][d];  V: bf16 h/l TRANSPOSED [bh][d][pos].
__global__ __launch_bounds__(256) void qkv_mma_gemm(void) {
    extern __shared__ char sm[];
    int bm = blockIdx.y * 128, bn = blockIdx.x * 128;
    float acc[4][4][4];
    gemm_core3(g_xh, g_xl, g_wqh, g_wql, bm, bn, sm, acc);

    int tid = threadIdx.x, l = tid & 31, w = tid >> 5;
    int wm = (w >> 2) * 64, wn = (w & 3) * 32;

#pragma unroll
    for (int mf = 0; mf < 4; mf++) {
#pragma unroll
        for (int half = 0; half < 2; half++) {
            int row = bm + wm + mf * 16 + (l >> 2) + half * 8;
            int b = row >> 11;
            int tok = row & (Nn - 1);
#pragma unroll
            for (int nf = 0; nf < 4; nf++) {
                int col = bn + wn + nf * 8 + (l & 3) * 2;   // even
                float y0 = acc[mf][nf][half * 2 + 0];
                float y1 = acc[mf][nf][half * 2 + 1];
                int region = col >> 10;
                int cc = col & 1023;
                int h = cc >> 6;
                int dd = cc & 63;
                int bh = b * Hh + h;
                uint16_t h0, l0, h1, l1;
                if (region == 2) {
                    // V[tok][dd], V[tok][dd+1] -> transposed [bh][d][pos]
                    size_t vb = ((size_t)bh * Dd + dd) * Nn + tok;
                    fsplit(y0, h0, l0);
                    fsplit(y1, h1, l1);
                    g_vh[vb]      = h0;  g_vl[vb]      = l0;
                    g_vh[vb + Nn] = h1;  g_vl[vb + Nn] = l1;
                } else {
                    size_t base = ((size_t)bh * Nn + tok) * Dd;
                    int i1 = dd >> 1;
                    float cs = g_cos[tok * 32 + i1];
                    float sn = g_sin[tok * 32 + i1];
                    float r0 = y0 * cs - y1 * sn;
                    float r1 = y0 * sn + y1 * cs;
                    uint16_t* dh = region ? g_kh : g_qh;
                    uint16_t* dl = region ? g_kl : g_ql;
                    fsplit(r0, h0, l0);
                    fsplit(r1, h1, l1);
                    dh[base + i1]      = h0; dl[base + i1]      = l0;
                    dh[base + i1 + 32] = h1; dl[base + i1 + 32] = l1;
                }
            }
        }
    }
}

// ---------------- GEMM3: out = O @ WoutT + bias ------------------------------
__global__ __launch_bounds__(256) void out_mma_gemm(const float* __restrict__ bias,
                                                    float* __restrict__ out) {
    extern __shared__ char sm[];
    int bm = blockIdx.y * 128, bn = blockIdx.x * 128;
    float acc[4][4][4];
    gemm_core3(g_oh, g_ol, g_woh, g_wol, bm, bn, sm, acc);

    int tid = threadIdx.x, l = tid & 31, w = tid >> 5;
    int wm = (w >> 2) * 64, wn = (w & 3) * 32;

#pragma unroll
    for (int mf = 0; mf < 4; mf++) {
#pragma unroll
        for (int half = 0; half < 2; half++) {
            int row = bm + wm + mf * 16 + (l >> 2) + half * 8;
#pragma unroll
            for (int nf = 0; nf < 4; nf++) {
                int col = bn + wn + nf * 8 + (l & 3) * 2;
                float y0 = acc[mf][nf][half * 2 + 0] + bias[col];
                float y1 = acc[mf][nf][half * 2 + 1] + bias[col + 1];
                *(float2*)(out + (size_t)row * Cc + col) = make_float2(y0, y1);
            }
        }
    }
}

// ========== Flash attention: pre-split inputs, copy-only tile fill ==========
#define AP 72
#define AT_SMEM 73728

__global__ __launch_bounds__(256) void flash_mma_kernel() {
    extern __shared__ char sm[];
    uint16_t* sQh = (uint16_t*)sm;
    uint16_t* sQl = (uint16_t*)(sm + 18432);
    uint16_t* sKh = (uint16_t*)(sm + 36864);
    uint16_t* sKl = (uint16_t*)(sm + 46080);
    uint16_t* sVh = (uint16_t*)(sm + 55296);
    uint16_t* sVl = (uint16_t*)(sm + 64512);

    int tid = threadIdx.x, l = tid & 31, w = tid >> 5;
    int wm = w * 16;
    int bh = blockIdx.y;
    int qb = blockIdx.x;
    int b = bh >> 4, h = bh & 15;

    // ---- Q: direct copy of pre-split data ----
    const uint16_t* Qh = g_qh + ((size_t)bh * Nn + qb * 128) * Dd;
    const uint16_t* Ql = g_ql + ((size_t)bh * Nn + qb * 128) * Dd;
#pragma unroll
    for (int i = 0; i < 4; i++) {
        int idx = tid + 256 * i;
        int r = idx >> 3, g = idx & 7;     // row 0..127, 16B group 0..7
        size_t off = (size_t)r * Dd + g * 8;
        *(uint4*)&sQh[r * AP + g * 8] = *(const uint4*)(Qh + off);
        *(uint4*)&sQl[r * AP + g * 8] = *(const uint4*)(Ql + off);
    }

    float O[8][4];
#pragma unroll
    for (int nf = 0; nf < 8; nf++)
#pragma unroll
        for (int i = 0; i < 4; i++) O[nf][i] = 0.0f;
    float mrow[2] = {-1e30f, -1e30f};
    float lsum[2] = {0.0f, 0.0f};

    const uint16_t* Kph = g_kh + (size_t)bh * Nn * Dd;
    const uint16_t* Kpl = g_kl + (size_t)bh * Nn * Dd;
    const uint16_t* Vph = g_vh + (size_t)bh * Dd * Nn;   // [d][pos]
    const uint16_t* Vpl = g_vl + (size_t)bh * Dd * Nn;

    const int ntiles = 2 * qb + 2;
    uint4 rKh[2], rKl[2], rVh[2], rVl[2];
    // preload tile 0 into regs
#pragma unroll
    for (int i = 0; i < 2; i++) {
        int idx = tid + 256 * i;
        int r = idx >> 3, g = idx & 7;     // row 0..63, group 0..7
        rKh[i] = *(const uint4*)(Kph + (size_t)r * Dd + g * 8);
        rKl[i] = *(const uint4*)(Kpl + (size_t)r * Dd + g * 8);
        rVh[i] = *(const uint4*)(Vph + (size_t)r * Nn + g * 8);
        rVl[i] = *(const uint4*)(Vpl + (size_t)r * Nn + g * 8);
    }

    for (int t = 0; t < ntiles; t++) {
        __syncthreads();   // previous tile's smem reads complete
#pragma unroll
        for (int i = 0; i < 2; i++) {
            int idx = tid + 256 * i;
            int r = idx >> 3, g = idx & 7;
            *(uint4*)&sKh[r * AP + g * 8] = rKh[i];
            *(uint4*)&sKl[r * AP + g * 8] = rKl[i];
            *(uint4*)&sVh[r * AP + g * 8] = rVh[i];
            *(uint4*)&sVl[r * AP + g * 8] = rVl[i];
        }
        __syncthreads();
        if (t + 1 < ntiles) {
#pragma unroll
            for (int i = 0; i < 2; i++) {
                int idx = tid + 256 * i;
                int r = idx >> 3, g = idx & 7;
                rKh[i] = *(const uint4*)(Kph + (size_t)((t+1) * 64 + r) * Dd + g * 8);
                rKl[i] = *(const uint4*)(Kpl + (size_t)((t+1) * 64 + r) * Dd + g * 8);
                rVh[i] = *(const uint4*)(Vph + (size_t)r * Nn + (t+1) * 64 + g * 8);
                rVl[i] = *(const uint4*)(Vpl + (size_t)r * Nn + (t+1) * 64 + g * 8);
            }
        }

        // ---- S = Q K^T (bf16x3) ----
        float S[8][4];
#pragma unroll
        for (int nf = 0; nf < 8; nf++)
#pragma unroll
            for (int i = 0; i < 4; i++) S[nf][i] = 0.0f;

#pragma unroll
        for (int ks = 0; ks < 4; ks++) {
            int kc = ks * 16 + (l & 3) * 2;
            int r = wm + (l >> 2);
            uint32_t qh[4], ql[4];
            qh[0] = *(const uint32_t*)&sQh[(r    ) * AP + kc];
            qh[1] = *(const uint32_t*)&sQh[(r + 8) * AP + kc];
            qh[2] = *(const uint32_t*)&sQh[(r    ) * AP + kc + 8];
            qh[3] = *(const uint32_t*)&sQh[(r + 8) * AP + kc + 8];
            ql[0] = *(const uint32_t*)&sQl[(r    ) * AP + kc];
            ql[1] = *(const uint32_t*)&sQl[(r + 8) * AP + kc];
            ql[2] = *(const uint32_t*)&sQl[(r    ) * AP + kc + 8];
            ql[3] = *(const uint32_t*)&sQl[(r + 8) * AP + kc + 8];
#pragma unroll
            for (int nf = 0; nf < 8; nf++) {
                int n = nf * 8 + (l >> 2);
                uint32_t kh2[2], kl2[2];
                kh2[0] = *(const uint32_t*)&sKh[n * AP + kc];
                kh2[1] = *(const uint32_t*)&sKh[n * AP + kc + 8];
                kl2[0] = *(const uint32_t*)&sKl[n * AP + kc];
                kl2[1] = *(const uint32_t*)&sKl[n * AP + kc + 8];
                mma_bf16(S[nf], qh, kh2);
                mma_bf16(S[nf], ql, kh2);
                mma_bf16(S[nf], qh, kl2);
            }
        }

        // ---- scale + causal mask ----
        bool domask = (t >= 2 * qb);
#pragma unroll
        for (int nf = 0; nf < 8; nf++)
#pragma unroll
            for (int idx = 0; idx < 4; idx++) {
                float v = S[nf][idx] * SL2E;
                if (domask) {
                    int h2 = idx >> 1, ci = idx & 1;
                    int qg = qb * 128 + wm + (l >> 2) + h2 * 8;
                    int kg = t * 64 + nf * 8 + (l & 3) * 2 + ci;
                    if (kg > qg) v = -1e30f;
                }
                S[nf][idx] = v;
            }

        // ---- online softmax (base-2; quad shfl) ----
#pragma unroll
        for (int h2 = 0; h2 < 2; h2++) {
            float mx = -1e30f;
#pragma unroll
            for (int nf = 0; nf < 8; nf++)
                mx = fmaxf(mx, fmaxf(S[nf][h2*2], S[nf][h2*2+1]));
            mx = fmaxf(mx, __shfl_xor_sync(0xffffffffu, mx, 1));
            mx = fmaxf(mx, __shfl_xor_sync(0xffffffffu, mx, 2));
            float mnew = fmaxf(mrow[h2], mx);
            float scl = ex2(mrow[h2] - mnew);
            float sum = 0.0f;
#pragma unroll
            for (int nf = 0; nf < 8; nf++) {
                float p0 = ex2(S[nf][h2*2]   - mnew);
                float p1 = ex2(S[nf][h2*2+1] - mnew);
                S[nf][h2*2]   = p0;
                S[nf][h2*2+1] = p1;
                sum += p0 + p1;
            }
            sum += __shfl_xor_sync(0xffffffffu, sum, 1);
            sum += __shfl_xor_sync(0xffffffffu, sum, 2);
            lsum[h2] = lsum[h2] * scl + sum;
            mrow[h2] = mnew;
#pragma unroll
            for (int nf = 0; nf < 8; nf++) {
                O[nf][h2*2]   *= scl;
                O[nf][h2*2+1] *= scl;
            }
        }

        // ---- O += P V ----
#pragma unroll
        for (int ks = 0; ks < 4; ks++) {
            uint32_t ph[4], pl[4];
#pragma unroll
            for (int half = 0; half < 2; half++) {
#pragma unroll
                for (int rr = 0; rr < 2; rr++) {
                    float v0 = S[2*ks + half][rr*2];
                    float v1 = S[2*ks + half][rr*2 + 1];
                    uint16_t a0, b0, a1, b1;
                    fsplit(v0, a0, b0);
                    fsplit(v1, a1, b1);
                    ph[half*2 + rr] = (uint32_t)a0 | ((uint32_t)a1 << 16);
                    pl[half*2 + rr] = (uint32_t)b0 | ((uint32_t)b1 << 16);
                }
            }
            int kc = ks * 16 + (l & 3) * 2;
#pragma unroll
            for (int nf = 0; nf < 8; nf++) {
                int n = nf * 8 + (l >> 2);
                uint32_t vh2[2], vl2[2];
                vh2[0] = *(const uint32_t*)&sVh[n * AP + kc];
                vh2[1] = *(const uint32_t*)&sVh[n * AP + kc + 8];
                vl2[0] = *(const uint32_t*)&sVl[n * AP + kc];
                vl2[1] = *(const uint32_t*)&sVl[n * AP + kc + 8];
                mma_bf16(O[nf], ph, vh2);
                mma_bf16(O[nf], pl, vh2);
                mma_bf16(O[nf], ph, vl2);
            }
        }
    }

    // ---- finalize: O /= l, store bf16 h/l to g_oh/g_ol [m][c] ----
    float inv[2] = {1.0f / lsum[0], 1.0f / lsum[1]};
#pragma unroll
    for (int nf = 0; nf < 8; nf++)
#pragma unroll
        for (int idx = 0; idx < 4; idx++) {
            int h2 = idx >> 1, ci = idx & 1;
            int q = qb * 128 + wm + (l >> 2) + h2 * 8;
            int col = h * 64 + nf * 8 + (l & 3) * 2 + ci;
            size_t o = (size_t)(b * Nn + q) * Cc + col;
            uint16_t hh, ll;
            fsplit(O[nf][idx] * inv[h2], hh, ll);
            g_oh[o] = hh;
            g_ol[o] = ll;
        }
}

// ---------------- launch -----------------------------------------------------
extern "C" void kernel_launch(void* const* d_in, const int* in_sizes, int n_in,
                              void* d_out, int out_size)
{
    (void)in_sizes; (void)n_in; (void)out_size;
    const float* x    = (const float*)d_in[0];
    const float* Wqkv = (const float*)d_in[1];
    const float* Wout = (const float*)d_in[2];
    const float* bout = (const float*)d_in[3];
    float* out = (float*)d_out;

    cudaFuncSetAttribute(qkv_mma_gemm, cudaFuncAttributeMaxDynamicSharedMemorySize, GEMM_SMEM);
    cudaFuncSetAttribute(out_mma_gemm, cudaFuncAttributeMaxDynamicSharedMemorySize, GEMM_SMEM);
    cudaFuncSetAttribute(flash_mma_kernel, cudaFuncAttributeMaxDynamicSharedMemorySize, AT_SMEM);

    rope_init_kernel<<<(Nn * 32 + 255) / 256, 256>>>();
    split_x_kernel<<<(Mtot * Cc / 4) / 256, 256>>>(x);
    transpose_split_kernel<<<dim3(K3 / 32, Cc / 32), dim3(32, 8)>>>(Wqkv, Cc, K3, 0);
    transpose_split_kernel<<<dim3(Cc / 32, Cc / 32), dim3(32, 8)>>>(Wout, Cc, Cc, 1);
    qkv_mma_gemm<<<dim3(K3 / 128, Mtot / 128), 256, GEMM_SMEM>>>();
    flash_mma_kernel<<<dim3(Nn / 128, Bb * Hh), 256, AT_SMEM>>>();
    out_mma_gemm<<<dim3(Cc / 128, Mtot / 128), 256, GEMM_SMEM>>>(bout, out);
}

// round 13
// speedup vs baseline: 1.1079x; 1.0902x over previous
#include <cuda_runtime.h>
#include <cuda_bf16.h>
#include <math.h>
#include <stdint.h>

#define Bb 2
#define Nn 2048
#define Cc 1024
#define Hh 16
#define Dd 64
#define Mtot (Bb*Nn)     /* 4096 */
#define K3  (3*Cc)       /* 3072 */
#define SL2E 0.1803368801111244f   /* 0.125 * log2(e) */

// ---------------- scratch ----------------------------------------------------
__device__ __align__(16) uint16_t g_wqh[(size_t)K3*Cc], g_wql[(size_t)K3*Cc]; // WqkvT [n][k]
__device__ __align__(16) uint16_t g_woh[(size_t)Cc*Cc], g_wol[(size_t)Cc*Cc]; // WoutT [n][k]
__device__ __align__(16) uint16_t g_xh[(size_t)Mtot*Cc], g_xl[(size_t)Mtot*Cc]; // x split
__device__ __align__(16) uint16_t g_qh[(size_t)Bb*Hh*Nn*Dd], g_ql[(size_t)Bb*Hh*Nn*Dd]; // [bh][pos][d]
__device__ __align__(16) uint16_t g_kh[(size_t)Bb*Hh*Nn*Dd], g_kl[(size_t)Bb*Hh*Nn*Dd]; // [bh][pos][d]
__device__ __align__(16) uint16_t g_vh[(size_t)Bb*Hh*Nn*Dd], g_vl[(size_t)Bb*Hh*Nn*Dd]; // [bh][d][pos]
__device__ __align__(16) uint16_t g_oh[(size_t)Mtot*Cc], g_ol[(size_t)Mtot*Cc]; // attn out [m][c]
__device__ float g_cos[Nn*32], g_sin[Nn*32];

// ---------------- helpers ----------------------------------------------------
__device__ __forceinline__ uint32_t smem_u32(const void* p) {
    uint32_t a;
    asm("{ .reg .u64 t; cvta.to.shared.u64 t, %1; cvt.u32.u64 %0, t; }" : "=r"(a) : "l"(p));
    return a;
}
__device__ __forceinline__ void ldsm4(uint32_t* r, uint32_t addr) {
    asm volatile("ldmatrix.sync.aligned.m8n8.x4.shared.b16 {%0,%1,%2,%3}, [%4];"
        : "=r"(r[0]), "=r"(r[1]), "=r"(r[2]), "=r"(r[3]) : "r"(addr));
}
__device__ __forceinline__ void mma_bf16(float* c, const uint32_t* a, const uint32_t* b) {
    asm volatile("mma.sync.aligned.m16n8k16.row.col.f32.bf16.bf16.f32 "
        "{%0,%1,%2,%3}, {%4,%5,%6,%7}, {%8,%9}, {%0,%1,%2,%3};"
        : "+f"(c[0]), "+f"(c[1]), "+f"(c[2]), "+f"(c[3])
        : "r"(a[0]), "r"(a[1]), "r"(a[2]), "r"(a[3]), "r"(b[0]), "r"(b[1]));
}
__device__ __forceinline__ void fsplit(float x, uint16_t& h, uint16_t& lo) {
    __nv_bfloat16 hb = __float2bfloat16_rn(x);
    float r = x - __bfloat162float(hb);
    __nv_bfloat16 lb = __float2bfloat16_rn(r);
    h  = *(uint16_t*)&hb;
    lo = *(uint16_t*)&lb;
}
__device__ __forceinline__ float ex2(float x) {
    float y;
    asm("ex2.approx.ftz.f32 %0, %1;" : "=f"(y) : "f"(x));
    return y;
}

// ---------------- init kernels -----------------------------------------------
__global__ void rope_init_kernel() {
    int idx = blockIdx.x * blockDim.x + threadIdx.x;
    if (idx >= Nn * 32) return;
    int n = idx >> 5, i = idx & 31;
    float invf = powf(10000.0f, -(float)i / 32.0f);
    float f = (float)n * invf;
    g_cos[idx] = cosf(f);
    g_sin[idx] = sinf(f);
}

__global__ __launch_bounds__(256) void split_x_kernel(const float* __restrict__ xp) {
    size_t i = ((size_t)blockIdx.x * 256 + threadIdx.x) * 4;
    float4 v = *(const float4*)(xp + i);
    uint16_t h0,l0,h1,l1,h2,l2,h3,l3;
    fsplit(v.x, h0, l0); fsplit(v.y, h1, l1);
    fsplit(v.z, h2, l2); fsplit(v.w, h3, l3);
    *(uint2*)(g_xh + i) = make_uint2((uint32_t)h0 | ((uint32_t)h1 << 16),
                                     (uint32_t)h2 | ((uint32_t)h3 << 16));
    *(uint2*)(g_xl + i) = make_uint2((uint32_t)l0 | ((uint32_t)l1 << 16),
                                     (uint32_t)l2 | ((uint32_t)l3 << 16));
}

// W [R][C] -> T [C][R] (split hi/lo), device-selected destinations
// (GB300/ATS trap: never pass __device__ symbols from host).
__global__ void transpose_split_kernel(const float* __restrict__ W,
                                       int R, int C, int which) {
    uint16_t* __restrict__ Th = which ? g_woh : g_wqh;
    uint16_t* __restrict__ Tl = which ? g_wol : g_wql;
    __shared__ float tile[32][33];
    int bx = blockIdx.x * 32, by = blockIdx.y * 32;
    int tx = threadIdx.x, ty = threadIdx.y;
#pragma unroll
    for (int i = 0; i < 4; i++)
        tile[ty + 8*i][tx] = W[(size_t)(by + ty + 8*i) * C + bx + tx];
    __syncthreads();
#pragma unroll
    for (int i = 0; i < 4; i++) {
        float v = tile[tx][ty + 8*i];
        uint16_t h, l;
        fsplit(v, h, l);
        size_t o = (size_t)(bx + ty + 8*i) * R + by + tx;
        Th[o] = h; Tl[o] = l;
    }
}

// ====== bf16x3 GEMM core: pre-split operands, register-staged, 1 sync/iter ===
// 128x128 tile, BK=32, 256 threads (warps 2x4, warp tile 64x32), ldmatrix.
// Stage (40960 B): Ah 0 | Al 10240 | Bh 20480 | Bl 30720; row stride 80 B.
#define GEMM_SMEM 81920
#define GP 40

__device__ __forceinline__ void gemm_core4(
    const uint16_t* __restrict__ Ah, const uint16_t* __restrict__ Al,
    const uint16_t* __restrict__ Bh, const uint16_t* __restrict__ Bl,
    int bm, int bn, char* sm, float acc[4][4][4])
{
    int tid = threadIdx.x, l = tid & 31, w = tid >> 5;
    int wm = (w >> 2) * 64, wn = (w & 3) * 32;
    uint32_t sb0 = smem_u32(sm);

#pragma unroll
    for (int mf = 0; mf < 4; mf++)
#pragma unroll
        for (int nf = 0; nf < 4; nf++)
#pragma unroll
            for (int i = 0; i < 4; i++) acc[mf][nf][i] = 0.0f;

    uint4 rAh[2], rAl[2], rBh[2], rBl[2];

    auto load_regs = [&](int kt) {
#pragma unroll
        for (int i = 0; i < 2; i++) {
            int ch = tid + 256 * i;
            int r = ch >> 2, g = ch & 3;
            size_t offa = (size_t)(bm + r) * Cc + kt * 32 + g * 8;
            size_t offb = (size_t)(bn + r) * Cc + kt * 32 + g * 8;
            rAh[i] = *(const uint4*)(Ah + offa);
            rAl[i] = *(const uint4*)(Al + offa);
            rBh[i] = *(const uint4*)(Bh + offb);
            rBl[i] = *(const uint4*)(Bl + offb);
        }
    };
    auto store_smem = [&](int st) {
        char* s0 = sm + st * 40960;
#pragma unroll
        for (int i = 0; i < 2; i++) {
            int ch = tid + 256 * i;
            int r = ch >> 2, g = ch & 3;
            int d = r * 80 + g * 16;
            *(uint4*)(s0 + d)          = rAh[i];
            *(uint4*)(s0 + 10240 + d)  = rAl[i];
            *(uint4*)(s0 + 20480 + d)  = rBh[i];
            *(uint4*)(s0 + 30720 + d)  = rBl[i];
        }
    };

    load_regs(0);
    for (int kt = 0; kt < 32; kt++) {
        store_smem(kt & 1);
        __syncthreads();
        if (kt + 1 < 32) load_regs(kt + 1);

        uint32_t sb = sb0 + (kt & 1) * 40960;
#pragma unroll
        for (int ks = 0; ks < 2; ks++) {
            int k0 = ks * 16;
            uint32_t ah[4][4], al[4][4];
            uint32_t arow = (uint32_t)(wm + (l & 15));
            uint32_t acol = (uint32_t)(k0 + (l >> 4) * 8);
#pragma unroll
            for (int mf = 0; mf < 4; mf++) {
                uint32_t off = ((arow + mf * 16) * GP + acol) * 2;
                ldsm4(ah[mf], sb + off);
                ldsm4(al[mf], sb + 10240 + off);
            }
            uint32_t bh2[4][2], bl2[4][2];
            uint32_t brow = (uint32_t)(wn + (l >> 4) * 8 + (l & 7));
            uint32_t bcol = (uint32_t)(k0 + ((l >> 3) & 1) * 8);
#pragma unroll
            for (int p = 0; p < 2; p++) {
                uint32_t off = ((brow + p * 16) * GP + bcol) * 2;
                uint32_t tb[4];
                ldsm4(tb, sb + 20480 + off);
                bh2[2*p][0] = tb[0]; bh2[2*p][1] = tb[1];
                bh2[2*p+1][0] = tb[2]; bh2[2*p+1][1] = tb[3];
                ldsm4(tb, sb + 30720 + off);
                bl2[2*p][0] = tb[0]; bl2[2*p][1] = tb[1];
                bl2[2*p+1][0] = tb[2]; bl2[2*p+1][1] = tb[3];
            }
#pragma unroll
            for (int nf = 0; nf < 4; nf++)
#pragma unroll
                for (int mf = 0; mf < 4; mf++) {
                    mma_bf16(acc[mf][nf], ah[mf], bh2[nf]);
                    mma_bf16(acc[mf][nf], al[mf], bh2[nf]);
                    mma_bf16(acc[mf][nf], ah[mf], bl2[nf]);
                }
        }
        // no trailing sync: iter kt+1 stores stage (kt+1)&1, whose last reads
        // were in iter kt-1, ordered before this iteration's sync.
    }
}

// ---------------- GEMM1: qkv + RoPE epilogue, writes pre-split Q/K/V ---------
__global__ __launch_bounds__(256) void qkv_mma_gemm(void) {
    extern __shared__ char sm[];
    int bm = blockIdx.y * 128, bn = blockIdx.x * 128;
    float acc[4][4][4];
    gemm_core4(g_xh, g_xl, g_wqh, g_wql, bm, bn, sm, acc);

    int tid = threadIdx.x, l = tid & 31, w = tid >> 5;
    int wm = (w >> 2) * 64, wn = (w & 3) * 32;

#pragma unroll
    for (int mf = 0; mf < 4; mf++) {
#pragma unroll
        for (int half = 0; half < 2; half++) {
            int row = bm + wm + mf * 16 + (l >> 2) + half * 8;
            int b = row >> 11;
            int tok = row & (Nn - 1);
#pragma unroll
            for (int nf = 0; nf < 4; nf++) {
                int col = bn + wn + nf * 8 + (l & 3) * 2;   // even
                float y0 = acc[mf][nf][half * 2 + 0];
                float y1 = acc[mf][nf][half * 2 + 1];
                int region = col >> 10;
                int cc = col & 1023;
                int h = cc >> 6;
                int dd = cc & 63;
                int bh = b * Hh + h;
                uint16_t h0, l0, h1, l1;
                if (region == 2) {
                    size_t vb = ((size_t)bh * Dd + dd) * Nn + tok;
                    fsplit(y0, h0, l0);
                    fsplit(y1, h1, l1);
                    g_vh[vb]      = h0;  g_vl[vb]      = l0;
                    g_vh[vb + Nn] = h1;  g_vl[vb + Nn] = l1;
                } else {
                    size_t base = ((size_t)bh * Nn + tok) * Dd;
                    int i1 = dd >> 1;
                    float cs = g_cos[tok * 32 + i1];
                    float sn = g_sin[tok * 32 + i1];
                    float r0 = y0 * cs - y1 * sn;
                    float r1 = y0 * sn + y1 * cs;
                    uint16_t* dh = region ? g_kh : g_qh;
                    uint16_t* dl = region ? g_kl : g_ql;
                    fsplit(r0, h0, l0);
                    fsplit(r1, h1, l1);
                    dh[base + i1]      = h0; dl[base + i1]      = l0;
                    dh[base + i1 + 32] = h1; dl[base + i1 + 32] = l1;
                }
            }
        }
    }
}

// ---------------- GEMM3: out = O @ WoutT + bias ------------------------------
__global__ __launch_bounds__(256) void out_mma_gemm(const float* __restrict__ bias,
                                                    float* __restrict__ out) {
    extern __shared__ char sm[];
    int bm = blockIdx.y * 128, bn = blockIdx.x * 128;
    float acc[4][4][4];
    gemm_core4(g_oh, g_ol, g_woh, g_wol, bm, bn, sm, acc);

    int tid = threadIdx.x, l = tid & 31, w = tid >> 5;
    int wm = (w >> 2) * 64, wn = (w & 3) * 32;

#pragma unroll
    for (int mf = 0; mf < 4; mf++) {
#pragma unroll
        for (int half = 0; half < 2; half++) {
            int row = bm + wm + mf * 16 + (l >> 2) + half * 8;
#pragma unroll
            for (int nf = 0; nf < 4; nf++) {
                int col = bn + wn + nf * 8 + (l & 3) * 2;
                float y0 = acc[mf][nf][half * 2 + 0] + bias[col];
                float y1 = acc[mf][nf][half * 2 + 1] + bias[col + 1];
                *(float2*)(out + (size_t)row * Cc + col) = make_float2(y0, y1);
            }
        }
    }
}

// ========== Flash attention: pre-split inputs, 2-stage KV, 1 sync/tile =======
// Smem: Qh 0 (18432) Ql 18432 | KV stage s at 36864 + s*36864:
//   Kh +0, Kl +9216, Vh +18432, Vl +27648.   Total 110592 B.
#define AP 72
#define AT_SMEM 110592

__global__ __launch_bounds__(256) void flash_mma_kernel() {
    extern __shared__ char sm[];
    uint16_t* sQh = (uint16_t*)sm;
    uint16_t* sQl = (uint16_t*)(sm + 18432);

    int tid = threadIdx.x, l = tid & 31, w = tid >> 5;
    int wm = w * 16;
    int bh = blockIdx.y;
    int qb = blockIdx.x;
    int b = bh >> 4, h = bh & 15;

    // ---- Q: direct copy of pre-split data ----
    const uint16_t* Qh = g_qh + ((size_t)bh * Nn + qb * 128) * Dd;
    const uint16_t* Ql = g_ql + ((size_t)bh * Nn + qb * 128) * Dd;
#pragma unroll
    for (int i = 0; i < 4; i++) {
        int idx = tid + 256 * i;
        int r = idx >> 3, g = idx & 7;
        size_t off = (size_t)r * Dd + g * 8;
        *(uint4*)&sQh[r * AP + g * 8] = *(const uint4*)(Qh + off);
        *(uint4*)&sQl[r * AP + g * 8] = *(const uint4*)(Ql + off);
    }

    float O[8][4];
#pragma unroll
    for (int nf = 0; nf < 8; nf++)
#pragma unroll
        for (int i = 0; i < 4; i++) O[nf][i] = 0.0f;
    float mrow[2] = {-1e30f, -1e30f};
    float lsum[2] = {0.0f, 0.0f};

    const uint16_t* Kph = g_kh + (size_t)bh * Nn * Dd;
    const uint16_t* Kpl = g_kl + (size_t)bh * Nn * Dd;
    const uint16_t* Vph = g_vh + (size_t)bh * Dd * Nn;   // [d][pos]
    const uint16_t* Vpl = g_vl + (size_t)bh * Dd * Nn;

    uint4 rKh[2], rKl[2], rVh[2], rVl[2];
    auto load_kv = [&](int t) {
#pragma unroll
        for (int i = 0; i < 2; i++) {
            int idx = tid + 256 * i;
            int r = idx >> 3, g = idx & 7;
            rKh[i] = *(const uint4*)(Kph + (size_t)(t * 64 + r) * Dd + g * 8);
            rKl[i] = *(const uint4*)(Kpl + (size_t)(t * 64 + r) * Dd + g * 8);
            rVh[i] = *(const uint4*)(Vph + (size_t)r * Nn + t * 64 + g * 8);
            rVl[i] = *(const uint4*)(Vpl + (size_t)r * Nn + t * 64 + g * 8);
        }
    };
    auto store_kv = [&](int st) {
        char* s0 = sm + 36864 + st * 36864;
#pragma unroll
        for (int i = 0; i < 2; i++) {
            int idx = tid + 256 * i;
            int r = idx >> 3, g = idx & 7;
            int d = r * (AP*2) + g * 16;
            *(uint4*)(s0 + d)          = rKh[i];
            *(uint4*)(s0 + 9216 + d)   = rKl[i];
            *(uint4*)(s0 + 18432 + d)  = rVh[i];
            *(uint4*)(s0 + 27648 + d)  = rVl[i];
        }
    };

    const int ntiles = 2 * qb + 2;
    load_kv(0);
    store_kv(0);
    __syncthreads();

    for (int t = 0; t < ntiles; t++) {
        if (t + 1 < ntiles) load_kv(t + 1);      // gmem -> regs (hidden by MMAs)

        const char* s0 = sm + 36864 + (t & 1) * 36864;
        const uint16_t* sKh = (const uint16_t*)(s0);
        const uint16_t* sKl = (const uint16_t*)(s0 + 9216);
        const uint16_t* sVh = (const uint16_t*)(s0 + 18432);
        const uint16_t* sVl = (const uint16_t*)(s0 + 27648);

        // ---- S = Q K^T (bf16x3) ----
        float S[8][4];
#pragma unroll
        for (int nf = 0; nf < 8; nf++)
#pragma unroll
            for (int i = 0; i < 4; i++) S[nf][i] = 0.0f;

#pragma unroll
        for (int ks = 0; ks < 4; ks++) {
            int kc = ks * 16 + (l & 3) * 2;
            int r = wm + (l >> 2);
            uint32_t qh[4], ql[4];
            qh[0] = *(const uint32_t*)&sQh[(r    ) * AP + kc];
            qh[1] = *(const uint32_t*)&sQh[(r + 8) * AP + kc];
            qh[2] = *(const uint32_t*)&sQh[(r    ) * AP + kc + 8];
            qh[3] = *(const uint32_t*)&sQh[(r + 8) * AP + kc + 8];
            ql[0] = *(const uint32_t*)&sQl[(r    ) * AP + kc];
            ql[1] = *(const uint32_t*)&sQl[(r + 8) * AP + kc];
            ql[2] = *(const uint32_t*)&sQl[(r    ) * AP + kc + 8];
            ql[3] = *(const uint32_t*)&sQl[(r + 8) * AP + kc + 8];
#pragma unroll
            for (int nf = 0; nf < 8; nf++) {
                int n = nf * 8 + (l >> 2);
                uint32_t kh2[2], kl2[2];
                kh2[0] = *(const uint32_t*)&sKh[n * AP + kc];
                kh2[1] = *(const uint32_t*)&sKh[n * AP + kc + 8];
                kl2[0] = *(const uint32_t*)&sKl[n * AP + kc];
                kl2[1] = *(const uint32_t*)&sKl[n * AP + kc + 8];
                mma_bf16(S[nf], qh, kh2);
                mma_bf16(S[nf], ql, kh2);
                mma_bf16(S[nf], qh, kl2);
            }
        }

        // ---- scale + causal mask ----
        bool domask = (t >= 2 * qb);
#pragma unroll
        for (int nf = 0; nf < 8; nf++)
#pragma unroll
            for (int idx = 0; idx < 4; idx++) {
                float v = S[nf][idx] * SL2E;
                if (domask) {
                    int h2 = idx >> 1, ci = idx & 1;
                    int qg = qb * 128 + wm + (l >> 2) + h2 * 8;
                    int kg = t * 64 + nf * 8 + (l & 3) * 2 + ci;
                    if (kg > qg) v = -1e30f;
                }
                S[nf][idx] = v;
            }

        // ---- online softmax (base-2; quad shfl) ----
#pragma unroll
        for (int h2 = 0; h2 < 2; h2++) {
            float mx = -1e30f;
#pragma unroll
            for (int nf = 0; nf < 8; nf++)
                mx = fmaxf(mx, fmaxf(S[nf][h2*2], S[nf][h2*2+1]));
            mx = fmaxf(mx, __shfl_xor_sync(0xffffffffu, mx, 1));
            mx = fmaxf(mx, __shfl_xor_sync(0xffffffffu, mx, 2));
            float mnew = fmaxf(mrow[h2], mx);
            float scl = ex2(mrow[h2] - mnew);
            float sum = 0.0f;
#pragma unroll
            for (int nf = 0; nf < 8; nf++) {
                float p0 = ex2(S[nf][h2*2]   - mnew);
                float p1 = ex2(S[nf][h2*2+1] - mnew);
                S[nf][h2*2]   = p0;
                S[nf][h2*2+1] = p1;
                sum += p0 + p1;
            }
            sum += __shfl_xor_sync(0xffffffffu, sum, 1);
            sum += __shfl_xor_sync(0xffffffffu, sum, 2);
            lsum[h2] = lsum[h2] * scl + sum;
            mrow[h2] = mnew;
#pragma unroll
            for (int nf = 0; nf < 8; nf++) {
                O[nf][h2*2]   *= scl;
                O[nf][h2*2+1] *= scl;
            }
        }

        // ---- O += P V ----
#pragma unroll
        for (int ks = 0; ks < 4; ks++) {
            uint32_t ph[4], pl[4];
#pragma unroll
            for (int half = 0; half < 2; half++) {
#pragma unroll
                for (int rr = 0; rr < 2; rr++) {
                    float v0 = S[2*ks + half][rr*2];
                    float v1 = S[2*ks + half][rr*2 + 1];
                    uint16_t a0, b0, a1, b1;
                    fsplit(v0, a0, b0);
                    fsplit(v1, a1, b1);
                    ph[half*2 + rr] = (uint32_t)a0 | ((uint32_t)a1 << 16);
                    pl[half*2 + rr] = (uint32_t)b0 | ((uint32_t)b1 << 16);
                }
            }
            int kc = ks * 16 + (l & 3) * 2;
#pragma unroll
            for (int nf = 0; nf < 8; nf++) {
                int n = nf * 8 + (l >> 2);
                uint32_t vh2[2], vl2[2];
                vh2[0] = *(const uint32_t*)&sVh[n * AP + kc];
                vh2[1] = *(const uint32_t*)&sVh[n * AP + kc + 8];
                vl2[0] = *(const uint32_t*)&sVl[n * AP + kc];
                vl2[1] = *(const uint32_t*)&sVl[n * AP + kc + 8];
                mma_bf16(O[nf], ph, vh2);
                mma_bf16(O[nf], pl, vh2);
                mma_bf16(O[nf], ph, vl2);
            }
        }

        if (t + 1 < ntiles) store_kv((t + 1) & 1);  // regs -> other stage
        __syncthreads();
    }

    // ---- finalize: O /= l, store bf16 h/l to g_oh/g_ol [m][c] ----
    float inv[2] = {1.0f / lsum[0], 1.0f / lsum[1]};
#pragma unroll
    for (int nf = 0; nf < 8; nf++)
#pragma unroll
        for (int idx = 0; idx < 4; idx++) {
            int h2 = idx >> 1, ci = idx & 1;
            int q = qb * 128 + wm + (l >> 2) + h2 * 8;
            int col = h * 64 + nf * 8 + (l & 3) * 2 + ci;
            size_t o = (size_t)(b * Nn + q) * Cc + col;
            uint16_t hh, ll;
            fsplit(O[nf][idx] * inv[h2], hh, ll);
            g_oh[o] = hh;
            g_ol[o] = ll;
        }
}

// ---------------- launch -----------------------------------------------------
extern "C" void kernel_launch(void* const* d_in, const int* in_sizes, int n_in,
                              void* d_out, int out_size)
{
    (void)in_sizes; (void)n_in; (void)out_size;
    const float* x    = (const float*)d_in[0];
    const float* Wqkv = (const float*)d_in[1];
    const float* Wout = (const float*)d_in[2];
    const float* bout = (const float*)d_in[3];
    float* out = (float*)d_out;

    cudaFuncSetAttribute(qkv_mma_gemm, cudaFuncAttributeMaxDynamicSharedMemorySize, GEMM_SMEM);
    cudaFuncSetAttribute(out_mma_gemm, cudaFuncAttributeMaxDynamicSharedMemorySize, GEMM_SMEM);
    cudaFuncSetAttribute(flash_mma_kernel, cudaFuncAttributeMaxDynamicSharedMemorySize, AT_SMEM);

    rope_init_kernel<<<(Nn * 32 + 255) / 256, 256>>>();
    split_x_kernel<<<(Mtot * Cc / 4) / 256, 256>>>(x);
    transpose_split_kernel<<<dim3(K3 / 32, Cc / 32), dim3(32, 8)>>>(Wqkv, Cc, K3, 0);
    transpose_split_kernel<<<dim3(Cc / 32, Cc / 32), dim3(32, 8)>>>(Wout, Cc, Cc, 1);
    qkv_mma_gemm<<<dim3(K3 / 128, Mtot / 128), 256, GEMM_SMEM>>>();
    flash_mma_kernel<<<dim3(Nn / 128, Bb * Hh), 256, AT_SMEM>>>();
    out_mma_gemm<<<dim3(Cc / 128, Mtot / 128), 256, GEMM_SMEM>>>(bout, out);
}

// round 14
// speedup vs baseline: 1.2158x; 1.0975x over previous
#include <cuda_runtime.h>
#include <cuda_bf16.h>
#include <math.h>
#include <stdint.h>

#define Bb 2
#define Nn 2048
#define Cc 1024
#define Hh 16
#define Dd 64
#define Mtot (Bb*Nn)     /* 4096 */
#define K3  (3*Cc)       /* 3072 */
#define SL2E 0.1803368801111244f   /* 0.125 * log2(e) */

// ---------------- scratch ----------------------------------------------------
__device__ __align__(16) uint16_t g_wqh[(size_t)K3*Cc], g_wql[(size_t)K3*Cc]; // WqkvT [n][k]
__device__ __align__(16) uint16_t g_woh[(size_t)Cc*Cc], g_wol[(size_t)Cc*Cc]; // WoutT [n][k]
__device__ __align__(16) uint16_t g_xh[(size_t)Mtot*Cc], g_xl[(size_t)Mtot*Cc]; // x split
__device__ __align__(16) uint16_t g_qh[(size_t)Bb*Hh*Nn*Dd], g_ql[(size_t)Bb*Hh*Nn*Dd]; // [bh][pos][d]
__device__ __align__(16) uint16_t g_kh[(size_t)Bb*Hh*Nn*Dd], g_kl[(size_t)Bb*Hh*Nn*Dd]; // [bh][pos][d]
__device__ __align__(16) uint16_t g_vh[(size_t)Bb*Hh*Nn*Dd], g_vl[(size_t)Bb*Hh*Nn*Dd]; // [bh][d][pos]
__device__ __align__(16) uint16_t g_oh[(size_t)Mtot*Cc], g_ol[(size_t)Mtot*Cc]; // attn out [m][c]
__device__ float g_cos[Nn*32], g_sin[Nn*32];

// ---------------- helpers ----------------------------------------------------
__device__ __forceinline__ uint32_t smem_u32(const void* p) {
    uint32_t a;
    asm("{ .reg .u64 t; cvta.to.shared.u64 t, %1; cvt.u32.u64 %0, t; }" : "=r"(a) : "l"(p));
    return a;
}
__device__ __forceinline__ void cpa16(uint32_t s, const void* g) {
    asm volatile("cp.async.cg.shared.global [%0], [%1], 16;" :: "r"(s), "l"(g) : "memory");
}
#define CP_COMMIT() asm volatile("cp.async.commit_group;" ::: "memory")
#define CP_WAIT0()  asm volatile("cp.async.wait_group 0;" ::: "memory")

__device__ __forceinline__ void ldsm4(uint32_t* r, uint32_t addr) {
    asm volatile("ldmatrix.sync.aligned.m8n8.x4.shared.b16 {%0,%1,%2,%3}, [%4];"
        : "=r"(r[0]), "=r"(r[1]), "=r"(r[2]), "=r"(r[3]) : "r"(addr));
}
__device__ __forceinline__ void mma_bf16(float* c, const uint32_t* a, const uint32_t* b) {
    asm volatile("mma.sync.aligned.m16n8k16.row.col.f32.bf16.bf16.f32 "
        "{%0,%1,%2,%3}, {%4,%5,%6,%7}, {%8,%9}, {%0,%1,%2,%3};"
        : "+f"(c[0]), "+f"(c[1]), "+f"(c[2]), "+f"(c[3])
        : "r"(a[0]), "r"(a[1]), "r"(a[2]), "r"(a[3]), "r"(b[0]), "r"(b[1]));
}
__device__ __forceinline__ void fsplit(float x, uint16_t& h, uint16_t& lo) {
    __nv_bfloat16 hb = __float2bfloat16_rn(x);
    float r = x - __bfloat162float(hb);
    __nv_bfloat16 lb = __float2bfloat16_rn(r);
    h  = *(uint16_t*)&hb;
    lo = *(uint16_t*)&lb;
}
__device__ __forceinline__ float ex2(float x) {
    float y;
    asm("ex2.approx.ftz.f32 %0, %1;" : "=f"(y) : "f"(x));
    return y;
}

// ---------------- init kernels -----------------------------------------------
__global__ void rope_init_kernel() {
    int idx = blockIdx.x * blockDim.x + threadIdx.x;
    if (idx >= Nn * 32) return;
    int n = idx >> 5, i = idx & 31;
    float invf = powf(10000.0f, -(float)i / 32.0f);
    float f = (float)n * invf;
    g_cos[idx] = cosf(f);
    g_sin[idx] = sinf(f);
}

__global__ __launch_bounds__(256) void split_x_kernel(const float* __restrict__ xp) {
    size_t i = ((size_t)blockIdx.x * 256 + threadIdx.x) * 4;
    float4 v = *(const float4*)(xp + i);
    uint16_t h0,l0,h1,l1,h2,l2,h3,l3;
    fsplit(v.x, h0, l0); fsplit(v.y, h1, l1);
    fsplit(v.z, h2, l2); fsplit(v.w, h3, l3);
    *(uint2*)(g_xh + i) = make_uint2((uint32_t)h0 | ((uint32_t)h1 << 16),
                                     (uint32_t)h2 | ((uint32_t)h3 << 16));
    *(uint2*)(g_xl + i) = make_uint2((uint32_t)l0 | ((uint32_t)l1 << 16),
                                     (uint32_t)l2 | ((uint32_t)l3 << 16));
}

// W [R][C] -> T [C][R] (split hi/lo), device-selected destinations
// (GB300/ATS trap: never pass __device__ symbols from host).
__global__ void transpose_split_kernel(const float* __restrict__ W,
                                       int R, int C, int which) {
    uint16_t* __restrict__ Th = which ? g_woh : g_wqh;
    uint16_t* __restrict__ Tl = which ? g_wol : g_wql;
    __shared__ float tile[32][33];
    int bx = blockIdx.x * 32, by = blockIdx.y * 32;
    int tx = threadIdx.x, ty = threadIdx.y;
#pragma unroll
    for (int i = 0; i < 4; i++)
        tile[ty + 8*i][tx] = W[(size_t)(by + ty + 8*i) * C + bx + tx];
    __syncthreads();
#pragma unroll
    for (int i = 0; i < 4; i++) {
        float v = tile[tx][ty + 8*i];
        uint16_t h, l;
        fsplit(v, h, l);
        size_t o = (size_t)(bx + ty + 8*i) * R + by + tx;
        Th[o] = h; Tl[o] = l;
    }
}

// == bf16x3 GEMM core: BK=64, 2-stage cp.async, 1 sync/iter, ldmatrix =========
// Stage (73728 B): Ah 0 | Al 18432 | Bh 36864 | Bl 55296; row stride 144 B.
#define GEMM_SMEM 147456
#define GP2 72

__device__ __forceinline__ void gemm_core5(
    const uint16_t* __restrict__ Ah, const uint16_t* __restrict__ Al,
    const uint16_t* __restrict__ Bh, const uint16_t* __restrict__ Bl,
    int bm, int bn, char* sm, float acc[4][4][4])
{
    int tid = threadIdx.x, l = tid & 31, w = tid >> 5;
    int wm = (w >> 2) * 64, wn = (w & 3) * 32;
    uint32_t sb0 = smem_u32(sm);

#pragma unroll
    for (int mf = 0; mf < 4; mf++)
#pragma unroll
        for (int nf = 0; nf < 4; nf++)
#pragma unroll
            for (int i = 0; i < 4; i++) acc[mf][nf][i] = 0.0f;

    auto issue = [&](int st, int kt) {
        uint32_t s0 = sb0 + st * 73728;
#pragma unroll
        for (int i = 0; i < 4; i++) {
            int ch = tid + 256 * i;
            int r = ch >> 3, g = ch & 7;       // row 0..127, 16B group 0..7 (64k*2B=128B)
            uint32_t d = s0 + r * 144 + g * 16;
            size_t offa = (size_t)(bm + r) * Cc + kt * 64 + g * 8;
            size_t offb = (size_t)(bn + r) * Cc + kt * 64 + g * 8;
            cpa16(d,          Ah + offa);
            cpa16(d + 18432,  Al + offa);
            cpa16(d + 36864,  Bh + offb);
            cpa16(d + 55296,  Bl + offb);
        }
    };

    issue(0, 0); CP_COMMIT();
    for (int kt = 0; kt < 16; kt++) {
        CP_WAIT0();
        __syncthreads();
        if (kt + 1 < 16) { issue((kt + 1) & 1, kt + 1); CP_COMMIT(); }

        uint32_t sb = sb0 + (kt & 1) * 73728;
#pragma unroll
        for (int ks = 0; ks < 4; ks++) {
            int k0 = ks * 16;
            uint32_t ah[4][4], al[4][4];
            uint32_t arow = (uint32_t)(wm + (l & 15));
            uint32_t acol = (uint32_t)(k0 + (l >> 4) * 8);
#pragma unroll
            for (int mf = 0; mf < 4; mf++) {
                uint32_t off = ((arow + mf * 16) * GP2 + acol) * 2;
                ldsm4(ah[mf], sb + off);
                ldsm4(al[mf], sb + 18432 + off);
            }
            uint32_t bh2[4][2], bl2[4][2];
            uint32_t brow = (uint32_t)(wn + (l >> 4) * 8 + (l & 7));
            uint32_t bcol = (uint32_t)(k0 + ((l >> 3) & 1) * 8);
#pragma unroll
            for (int p = 0; p < 2; p++) {
                uint32_t off = ((brow + p * 16) * GP2 + bcol) * 2;
                uint32_t tb[4];
                ldsm4(tb, sb + 36864 + off);
                bh2[2*p][0] = tb[0]; bh2[2*p][1] = tb[1];
                bh2[2*p+1][0] = tb[2]; bh2[2*p+1][1] = tb[3];
                ldsm4(tb, sb + 55296 + off);
                bl2[2*p][0] = tb[0]; bl2[2*p][1] = tb[1];
                bl2[2*p+1][0] = tb[2]; bl2[2*p+1][1] = tb[3];
            }
#pragma unroll
            for (int nf = 0; nf < 4; nf++)
#pragma unroll
                for (int mf = 0; mf < 4; mf++) {
                    mma_bf16(acc[mf][nf], ah[mf], bh2[nf]);
                    mma_bf16(acc[mf][nf], al[mf], bh2[nf]);
                    mma_bf16(acc[mf][nf], ah[mf], bl2[nf]);
                }
        }
        // single sync: stage (kt+1)&1 was last read in iter kt-1, whose reads
        // precede this iteration's sync; cp.async into it is safe.
    }
}

// ---------------- GEMM1: qkv + RoPE epilogue, writes pre-split Q/K/V ---------
__global__ __launch_bounds__(256) void qkv_mma_gemm(void) {
    extern __shared__ char sm[];
    int bm = blockIdx.y * 128, bn = blockIdx.x * 128;
    float acc[4][4][4];
    gemm_core5(g_xh, g_xl, g_wqh, g_wql, bm, bn, sm, acc);

    int tid = threadIdx.x, l = tid & 31, w = tid >> 5;
    int wm = (w >> 2) * 64, wn = (w & 3) * 32;

#pragma unroll
    for (int mf = 0; mf < 4; mf++) {
#pragma unroll
        for (int half = 0; half < 2; half++) {
            int row = bm + wm + mf * 16 + (l >> 2) + half * 8;
            int b = row >> 11;
            int tok = row & (Nn - 1);
#pragma unroll
            for (int nf = 0; nf < 4; nf++) {
                int col = bn + wn + nf * 8 + (l & 3) * 2;   // even
                float y0 = acc[mf][nf][half * 2 + 0];
                float y1 = acc[mf][nf][half * 2 + 1];
                int region = col >> 10;
                int cc = col & 1023;
                int h = cc >> 6;
                int dd = cc & 63;
                int bh = b * Hh + h;
                uint16_t h0, l0, h1, l1;
                if (region == 2) {
                    size_t vb = ((size_t)bh * Dd + dd) * Nn + tok;
                    fsplit(y0, h0, l0);
                    fsplit(y1, h1, l1);
                    g_vh[vb]      = h0;  g_vl[vb]      = l0;
                    g_vh[vb + Nn] = h1;  g_vl[vb + Nn] = l1;
                } else {
                    size_t base = ((size_t)bh * Nn + tok) * Dd;
                    int i1 = dd >> 1;
                    float cs = g_cos[tok * 32 + i1];
                    float sn = g_sin[tok * 32 + i1];
                    float r0 = y0 * cs - y1 * sn;
                    float r1 = y0 * sn + y1 * cs;
                    uint16_t* dh = region ? g_kh : g_qh;
                    uint16_t* dl = region ? g_kl : g_ql;
                    fsplit(r0, h0, l0);
                    fsplit(r1, h1, l1);
                    dh[base + i1]      = h0; dl[base + i1]      = l0;
                    dh[base + i1 + 32] = h1; dl[base + i1 + 32] = l1;
                }
            }
        }
    }
}

// ---------------- GEMM3: out = O @ WoutT + bias ------------------------------
__global__ __launch_bounds__(256) void out_mma_gemm(const float* __restrict__ bias,
                                                    float* __restrict__ out) {
    extern __shared__ char sm[];
    int bm = blockIdx.y * 128, bn = blockIdx.x * 128;
    float acc[4][4][4];
    gemm_core5(g_oh, g_ol, g_woh, g_wol, bm, bn, sm, acc);

    int tid = threadIdx.x, l = tid & 31, w = tid >> 5;
    int wm = (w >> 2) * 64, wn = (w & 3) * 32;

#pragma unroll
    for (int mf = 0; mf < 4; mf++) {
#pragma unroll
        for (int half = 0; half < 2; half++) {
            int row = bm + wm + mf * 16 + (l >> 2) + half * 8;
#pragma unroll
            for (int nf = 0; nf < 4; nf++) {
                int col = bn + wn + nf * 8 + (l & 3) * 2;
                float y0 = acc[mf][nf][half * 2 + 0] + bias[col];
                float y1 = acc[mf][nf][half * 2 + 1] + bias[col + 1];
                *(float2*)(out + (size_t)row * Cc + col) = make_float2(y0, y1);
            }
        }
    }
}

// ========== Flash attention: cp.async KV, 2-stage, 1 sync/tile, 2 CTA/SM =====
// Smem: Qh 0 (18432) Ql 18432 | KV stage s at 36864 + s*36864:
//   Kh +0, Kl +9216, Vh +18432, Vl +27648.   Total 110592 B.
#define AP 72
#define AT_SMEM 110592

__global__ __launch_bounds__(256, 2) void flash_mma_kernel() {
    extern __shared__ char sm[];
    uint16_t* sQh = (uint16_t*)sm;
    uint16_t* sQl = (uint16_t*)(sm + 18432);
    uint32_t sb0 = smem_u32(sm);

    int tid = threadIdx.x, l = tid & 31, w = tid >> 5;
    int wm = w * 16;
    int bh = blockIdx.y;
    int qb = blockIdx.x;
    int b = bh >> 4, h = bh & 15;

    // ---- Q: direct copy of pre-split data ----
    const uint16_t* Qh = g_qh + ((size_t)bh * Nn + qb * 128) * Dd;
    const uint16_t* Ql = g_ql + ((size_t)bh * Nn + qb * 128) * Dd;
#pragma unroll
    for (int i = 0; i < 4; i++) {
        int idx = tid + 256 * i;
        int r = idx >> 3, g = idx & 7;
        size_t off = (size_t)r * Dd + g * 8;
        *(uint4*)&sQh[r * AP + g * 8] = *(const uint4*)(Qh + off);
        *(uint4*)&sQl[r * AP + g * 8] = *(const uint4*)(Ql + off);
    }

    float O[8][4];
#pragma unroll
    for (int nf = 0; nf < 8; nf++)
#pragma unroll
        for (int i = 0; i < 4; i++) O[nf][i] = 0.0f;
    float mrow[2] = {-1e30f, -1e30f};
    float lsum[2] = {0.0f, 0.0f};

    const uint16_t* Kph = g_kh + (size_t)bh * Nn * Dd;
    const uint16_t* Kpl = g_kl + (size_t)bh * Nn * Dd;
    const uint16_t* Vph = g_vh + (size_t)bh * Dd * Nn;   // [d][pos]
    const uint16_t* Vpl = g_vl + (size_t)bh * Dd * Nn;

    auto issue_kv = [&](int t, int st) {
        uint32_t s0 = sb0 + 36864 + st * 36864;
#pragma unroll
        for (int i = 0; i < 2; i++) {
            int idx = tid + 256 * i;
            int r = idx >> 3, g = idx & 7;    // row 0..63, group 0..7
            uint32_t d = s0 + r * 144 + g * 16;
            cpa16(d,          Kph + (size_t)(t * 64 + r) * Dd + g * 8);
            cpa16(d + 9216,   Kpl + (size_t)(t * 64 + r) * Dd + g * 8);
            cpa16(d + 18432,  Vph + (size_t)r * Nn + t * 64 + g * 8);
            cpa16(d + 27648,  Vpl + (size_t)r * Nn + t * 64 + g * 8);
        }
    };

    const int ntiles = 2 * qb + 2;
    issue_kv(0, 0); CP_COMMIT();

    for (int t = 0; t < ntiles; t++) {
        CP_WAIT0();
        __syncthreads();
        if (t + 1 < ntiles) { issue_kv(t + 1, (t + 1) & 1); CP_COMMIT(); }

        const char* s0 = sm + 36864 + (t & 1) * 36864;
        const uint16_t* sKh = (const uint16_t*)(s0);
        const uint16_t* sKl = (const uint16_t*)(s0 + 9216);
        const uint16_t* sVh = (const uint16_t*)(s0 + 18432);
        const uint16_t* sVl = (const uint16_t*)(s0 + 27648);

        // ---- S = Q K^T (bf16x3) ----
        float S[8][4];
#pragma unroll
        for (int nf = 0; nf < 8; nf++)
#pragma unroll
            for (int i = 0; i < 4; i++) S[nf][i] = 0.0f;

#pragma unroll
        for (int ks = 0; ks < 4; ks++) {
            int kc = ks * 16 + (l & 3) * 2;
            int r = wm + (l >> 2);
            uint32_t qh[4], ql[4];
            qh[0] = *(const uint32_t*)&sQh[(r    ) * AP + kc];
            qh[1] = *(const uint32_t*)&sQh[(r + 8) * AP + kc];
            qh[2] = *(const uint32_t*)&sQh[(r    ) * AP + kc + 8];
            qh[3] = *(const uint32_t*)&sQh[(r + 8) * AP + kc + 8];
            ql[0] = *(const uint32_t*)&sQl[(r    ) * AP + kc];
            ql[1] = *(const uint32_t*)&sQl[(r + 8) * AP + kc];
            ql[2] = *(const uint32_t*)&sQl[(r    ) * AP + kc + 8];
            ql[3] = *(const uint32_t*)&sQl[(r + 8) * AP + kc + 8];
#pragma unroll
            for (int nf = 0; nf < 8; nf++) {
                int n = nf * 8 + (l >> 2);
                uint32_t kh2[2], kl2[2];
                kh2[0] = *(const uint32_t*)&sKh[n * AP + kc];
                kh2[1] = *(const uint32_t*)&sKh[n * AP + kc + 8];
                kl2[0] = *(const uint32_t*)&sKl[n * AP + kc];
                kl2[1] = *(const uint32_t*)&sKl[n * AP + kc + 8];
                mma_bf16(S[nf], qh, kh2);
                mma_bf16(S[nf], ql, kh2);
                mma_bf16(S[nf], qh, kl2);
            }
        }

        // ---- scale + causal mask ----
        bool domask = (t >= 2 * qb);
#pragma unroll
        for (int nf = 0; nf < 8; nf++)
#pragma unroll
            for (int idx = 0; idx < 4; idx++) {
                float v = S[nf][idx] * SL2E;
                if (domask) {
                    int h2 = idx >> 1, ci = idx & 1;
                    int qg = qb * 128 + wm + (l >> 2) + h2 * 8;
                    int kg = t * 64 + nf * 8 + (l & 3) * 2 + ci;
                    if (kg > qg) v = -1e30f;
                }
                S[nf][idx] = v;
            }

        // ---- online softmax (base-2; quad shfl) ----
#pragma unroll
        for (int h2 = 0; h2 < 2; h2++) {
            float mx = -1e30f;
#pragma unroll
            for (int nf = 0; nf < 8; nf++)
                mx = fmaxf(mx, fmaxf(S[nf][h2*2], S[nf][h2*2+1]));
            mx = fmaxf(mx, __shfl_xor_sync(0xffffffffu, mx, 1));
            mx = fmaxf(mx, __shfl_xor_sync(0xffffffffu, mx, 2));
            float mnew = fmaxf(mrow[h2], mx);
            float scl = ex2(mrow[h2] - mnew);
            float sum = 0.0f;
#pragma unroll
            for (int nf = 0; nf < 8; nf++) {
                float p0 = ex2(S[nf][h2*2]   - mnew);
                float p1 = ex2(S[nf][h2*2+1] - mnew);
                S[nf][h2*2]   = p0;
                S[nf][h2*2+1] = p1;
                sum += p0 + p1;
            }
            sum += __shfl_xor_sync(0xffffffffu, sum, 1);
            sum += __shfl_xor_sync(0xffffffffu, sum, 2);
            lsum[h2] = lsum[h2] * scl + sum;
            mrow[h2] = mnew;
#pragma unroll
            for (int nf = 0; nf < 8; nf++) {
                O[nf][h2*2]   *= scl;
                O[nf][h2*2+1] *= scl;
            }
        }

        // ---- O += P V ----
#pragma unroll
        for (int ks = 0; ks < 4; ks++) {
            uint32_t ph[4], pl[4];
#pragma unroll
            for (int half = 0; half < 2; half++) {
#pragma unroll
                for (int rr = 0; rr < 2; rr++) {
                    float v0 = S[2*ks + half][rr*2];
                    float v1 = S[2*ks + half][rr*2 + 1];
                    uint16_t a0, b0, a1, b1;
                    fsplit(v0, a0, b0);
                    fsplit(v1, a1, b1);
                    ph[half*2 + rr] = (uint32_t)a0 | ((uint32_t)a1 << 16);
                    pl[half*2 + rr] = (uint32_t)b0 | ((uint32_t)b1 << 16);
                }
            }
            int kc = ks * 16 + (l & 3) * 2;
#pragma unroll
            for (int nf = 0; nf < 8; nf++) {
                int n = nf * 8 + (l >> 2);
                uint32_t vh2[2], vl2[2];
                vh2[0] = *(const uint32_t*)&sVh[n * AP + kc];
                vh2[1] = *(const uint32_t*)&sVh[n * AP + kc + 8];
                vl2[0] = *(const uint32_t*)&sVl[n * AP + kc];
                vl2[1] = *(const uint32_t*)&sVl[n * AP + kc + 8];
                mma_bf16(O[nf], ph, vh2);
                mma_bf16(O[nf], pl, vh2);
                mma_bf16(O[nf], ph, vl2);
            }
        }
    }

    // ---- finalize: O /= l, store bf16 h/l to g_oh/g_ol [m][c] ----
    float inv[2] = {1.0f / lsum[0], 1.0f / lsum[1]};
#pragma unroll
    for (int nf = 0; nf < 8; nf++)
#pragma unroll
        for (int idx = 0; idx < 4; idx++) {
            int h2 = idx >> 1, ci = idx & 1;
            int q = qb * 128 + wm + (l >> 2) + h2 * 8;
            int col = h * 64 + nf * 8 + (l & 3) * 2 + ci;
            size_t o = (size_t)(b * Nn + q) * Cc + col;
            uint16_t hh, ll;
            fsplit(O[nf][idx] * inv[h2], hh, ll);
            g_oh[o] = hh;
            g_ol[o] = ll;
        }
}

// ---------------- launch -----------------------------------------------------
extern "C" void kernel_launch(void* const* d_in, const int* in_sizes, int n_in,
                              void* d_out, int out_size)
{
    (void)in_sizes; (void)n_in; (void)out_size;
    const float* x    = (const float*)d_in[0];
    const float* Wqkv = (const float*)d_in[1];
    const float* Wout = (const float*)d_in[2];
    const float* bout = (const float*)d_in[3];
    float* out = (float*)d_out;

    cudaFuncSetAttribute(qkv_mma_gemm, cudaFuncAttributeMaxDynamicSharedMemorySize, GEMM_SMEM);
    cudaFuncSetAttribute(out_mma_gemm, cudaFuncAttributeMaxDynamicSharedMemorySize, GEMM_SMEM);
    cudaFuncSetAttribute(flash_mma_kernel, cudaFuncAttributeMaxDynamicSharedMemorySize, AT_SMEM);

    rope_init_kernel<<<(Nn * 32 + 255) / 256, 256>>>();
    split_x_kernel<<<(Mtot * Cc / 4) / 256, 256>>>(x);
    transpose_split_kernel<<<dim3(K3 / 32, Cc / 32), dim3(32, 8)>>>(Wqkv, Cc, K3, 0);
    transpose_split_kernel<<<dim3(Cc / 32, Cc / 32), dim3(32, 8)>>>(Wout, Cc, Cc, 1);
    qkv_mma_gemm<<<dim3(K3 / 128, Mtot / 128), 256, GEMM_SMEM>>>();
    flash_mma_kernel<<<dim3(Nn / 128, Bb * Hh), 256, AT_SMEM>>>();
    out_mma_gemm<<<dim3(Cc / 128, Mtot / 128), 256, GEMM_SMEM>>>(bout, out);
}

// round 15
// speedup vs baseline: 1.3189x; 1.0847x over previous
#include <cuda_runtime.h>
#include <cuda_bf16.h>
#include <math.h>
#include <stdint.h>

#define Bb 2
#define Nn 2048
#define Cc 1024
#define Hh 16
#define Dd 64
#define Mtot (Bb*Nn)     /* 4096 */
#define K3  (3*Cc)       /* 3072 */
#define NQB 16           /* q-tiles of 128 */
#define SL2E 0.1803368801111244f   /* 0.125 * log2(e) */

// ---------------- scratch ----------------------------------------------------
__device__ __align__(16) uint16_t g_wqh[(size_t)K3*Cc], g_wql[(size_t)K3*Cc]; // WqkvT [n][k]
__device__ __align__(16) uint16_t g_woh[(size_t)Cc*Cc], g_wol[(size_t)Cc*Cc]; // WoutT [n][k]
__device__ __align__(16) uint16_t g_xh[(size_t)Mtot*Cc], g_xl[(size_t)Mtot*Cc]; // x split
__device__ __align__(16) uint16_t g_qh[(size_t)Bb*Hh*Nn*Dd], g_ql[(size_t)Bb*Hh*Nn*Dd]; // [bh][pos][d]
__device__ __align__(16) uint16_t g_kh[(size_t)Bb*Hh*Nn*Dd], g_kl[(size_t)Bb*Hh*Nn*Dd]; // [bh][pos][d]
__device__ __align__(16) uint16_t g_vh[(size_t)Bb*Hh*Nn*Dd], g_vl[(size_t)Bb*Hh*Nn*Dd]; // [bh][d][pos]
__device__ __align__(16) uint16_t g_oh[(size_t)Mtot*Cc], g_ol[(size_t)Mtot*Cc]; // attn out [m][c]
__device__ float g_cos[Nn*32], g_sin[Nn*32];

// ---------------- helpers ----------------------------------------------------
__device__ __forceinline__ uint32_t smem_u32(const void* p) {
    uint32_t a;
    asm("{ .reg .u64 t; cvta.to.shared.u64 t, %1; cvt.u32.u64 %0, t; }" : "=r"(a) : "l"(p));
    return a;
}
__device__ __forceinline__ void cpa16(uint32_t s, const void* g) {
    asm volatile("cp.async.cg.shared.global [%0], [%1], 16;" :: "r"(s), "l"(g) : "memory");
}
#define CP_COMMIT() asm volatile("cp.async.commit_group;" ::: "memory")
#define CP_WAIT0()  asm volatile("cp.async.wait_group 0;" ::: "memory")

__device__ __forceinline__ void ldsm4(uint32_t* r, uint32_t addr) {
    asm volatile("ldmatrix.sync.aligned.m8n8.x4.shared.b16 {%0,%1,%2,%3}, [%4];"
        : "=r"(r[0]), "=r"(r[1]), "=r"(r[2]), "=r"(r[3]) : "r"(addr));
}
__device__ __forceinline__ void mma_bf16(float* c, const uint32_t* a, const uint32_t* b) {
    asm volatile("mma.sync.aligned.m16n8k16.row.col.f32.bf16.bf16.f32 "
        "{%0,%1,%2,%3}, {%4,%5,%6,%7}, {%8,%9}, {%0,%1,%2,%3};"
        : "+f"(c[0]), "+f"(c[1]), "+f"(c[2]), "+f"(c[3])
        : "r"(a[0]), "r"(a[1]), "r"(a[2]), "r"(a[3]), "r"(b[0]), "r"(b[1]));
}
__device__ __forceinline__ void fsplit(float x, uint16_t& h, uint16_t& lo) {
    __nv_bfloat16 hb = __float2bfloat16_rn(x);
    float r = x - __bfloat162float(hb);
    __nv_bfloat16 lb = __float2bfloat16_rn(r);
    h  = *(uint16_t*)&hb;
    lo = *(uint16_t*)&lb;
}
__device__ __forceinline__ float ex2(float x) {
    float y;
    asm("ex2.approx.ftz.f32 %0, %1;" : "=f"(y) : "f"(x));
    return y;
}

// ---------------- init kernels -----------------------------------------------
__global__ void rope_init_kernel() {
    int idx = blockIdx.x * blockDim.x + threadIdx.x;
    if (idx >= Nn * 32) return;
    int n = idx >> 5, i = idx & 31;
    float invf = powf(10000.0f, -(float)i / 32.0f);
    float f = (float)n * invf;
    g_cos[idx] = cosf(f);
    g_sin[idx] = sinf(f);
}

__global__ __launch_bounds__(256) void split_x_kernel(const float* __restrict__ xp) {
    size_t i = ((size_t)blockIdx.x * 256 + threadIdx.x) * 4;
    float4 v = *(const float4*)(xp + i);
    uint16_t h0,l0,h1,l1,h2,l2,h3,l3;
    fsplit(v.x, h0, l0); fsplit(v.y, h1, l1);
    fsplit(v.z, h2, l2); fsplit(v.w, h3, l3);
    *(uint2*)(g_xh + i) = make_uint2((uint32_t)h0 | ((uint32_t)h1 << 16),
                                     (uint32_t)h2 | ((uint32_t)h3 << 16));
    *(uint2*)(g_xl + i) = make_uint2((uint32_t)l0 | ((uint32_t)l1 << 16),
                                     (uint32_t)l2 | ((uint32_t)l3 << 16));
}

// W [R][C] -> T [C][R] (split hi/lo), device-selected destinations
// (GB300/ATS trap: never pass __device__ symbols from host).
__global__ void transpose_split_kernel(const float* __restrict__ W,
                                       int R, int C, int which) {
    uint16_t* __restrict__ Th = which ? g_woh : g_wqh;
    uint16_t* __restrict__ Tl = which ? g_wol : g_wql;
    __shared__ float tile[32][33];
    int bx = blockIdx.x * 32, by = blockIdx.y * 32;
    int tx = threadIdx.x, ty = threadIdx.y;
#pragma unroll
    for (int i = 0; i < 4; i++)
        tile[ty + 8*i][tx] = W[(size_t)(by + ty + 8*i) * C + bx + tx];
    __syncthreads();
#pragma unroll
    for (int i = 0; i < 4; i++) {
        float v = tile[tx][ty + 8*i];
        uint16_t h, l;
        fsplit(v, h, l);
        size_t o = (size_t)(bx + ty + 8*i) * R + by + tx;
        Th[o] = h; Tl[o] = l;
    }
}

// == bf16x3 GEMM core: BK=64, 2-stage cp.async, 1 sync/iter, ldmatrix =========
#define GEMM_SMEM 147456
#define GP2 72

__device__ __forceinline__ void gemm_core5(
    const uint16_t* __restrict__ Ah, const uint16_t* __restrict__ Al,
    const uint16_t* __restrict__ Bh, const uint16_t* __restrict__ Bl,
    int bm, int bn, char* sm, float acc[4][4][4])
{
    int tid = threadIdx.x, l = tid & 31, w = tid >> 5;
    int wm = (w >> 2) * 64, wn = (w & 3) * 32;
    uint32_t sb0 = smem_u32(sm);

#pragma unroll
    for (int mf = 0; mf < 4; mf++)
#pragma unroll
        for (int nf = 0; nf < 4; nf++)
#pragma unroll
            for (int i = 0; i < 4; i++) acc[mf][nf][i] = 0.0f;

    auto issue = [&](int st, int kt) {
        uint32_t s0 = sb0 + st * 73728;
#pragma unroll
        for (int i = 0; i < 4; i++) {
            int ch = tid + 256 * i;
            int r = ch >> 3, g = ch & 7;
            uint32_t d = s0 + r * 144 + g * 16;
            size_t offa = (size_t)(bm + r) * Cc + kt * 64 + g * 8;
            size_t offb = (size_t)(bn + r) * Cc + kt * 64 + g * 8;
            cpa16(d,          Ah + offa);
            cpa16(d + 18432,  Al + offa);
            cpa16(d + 36864,  Bh + offb);
            cpa16(d + 55296,  Bl + offb);
        }
    };

    issue(0, 0); CP_COMMIT();
    for (int kt = 0; kt < 16; kt++) {
        CP_WAIT0();
        __syncthreads();
        if (kt + 1 < 16) { issue((kt + 1) & 1, kt + 1); CP_COMMIT(); }

        uint32_t sb = sb0 + (kt & 1) * 73728;
#pragma unroll
        for (int ks = 0; ks < 4; ks++) {
            int k0 = ks * 16;
            uint32_t ah[4][4], al[4][4];
            uint32_t arow = (uint32_t)(wm + (l & 15));
            uint32_t acol = (uint32_t)(k0 + (l >> 4) * 8);
#pragma unroll
            for (int mf = 0; mf < 4; mf++) {
                uint32_t off = ((arow + mf * 16) * GP2 + acol) * 2;
                ldsm4(ah[mf], sb + off);
                ldsm4(al[mf], sb + 18432 + off);
            }
            uint32_t bh2[4][2], bl2[4][2];
            uint32_t brow = (uint32_t)(wn + (l >> 4) * 8 + (l & 7));
            uint32_t bcol = (uint32_t)(k0 + ((l >> 3) & 1) * 8);
#pragma unroll
            for (int p = 0; p < 2; p++) {
                uint32_t off = ((brow + p * 16) * GP2 + bcol) * 2;
                uint32_t tb[4];
                ldsm4(tb, sb + 36864 + off);
                bh2[2*p][0] = tb[0]; bh2[2*p][1] = tb[1];
                bh2[2*p+1][0] = tb[2]; bh2[2*p+1][1] = tb[3];
                ldsm4(tb, sb + 55296 + off);
                bl2[2*p][0] = tb[0]; bl2[2*p][1] = tb[1];
                bl2[2*p+1][0] = tb[2]; bl2[2*p+1][1] = tb[3];
            }
#pragma unroll
            for (int nf = 0; nf < 4; nf++)
#pragma unroll
                for (int mf = 0; mf < 4; mf++) {
                    mma_bf16(acc[mf][nf], ah[mf], bh2[nf]);
                    mma_bf16(acc[mf][nf], al[mf], bh2[nf]);
                    mma_bf16(acc[mf][nf], ah[mf], bl2[nf]);
                }
        }
    }
}

// ---------------- GEMM1: qkv + RoPE epilogue, writes pre-split Q/K/V ---------
__global__ __launch_bounds__(256) void qkv_mma_gemm(void) {
    extern __shared__ char sm[];
    int bm = blockIdx.y * 128, bn = blockIdx.x * 128;
    float acc[4][4][4];
    gemm_core5(g_xh, g_xl, g_wqh, g_wql, bm, bn, sm, acc);

    int tid = threadIdx.x, l = tid & 31, w = tid >> 5;
    int wm = (w >> 2) * 64, wn = (w & 3) * 32;

#pragma unroll
    for (int mf = 0; mf < 4; mf++) {
#pragma unroll
        for (int half = 0; half < 2; half++) {
            int row = bm + wm + mf * 16 + (l >> 2) + half * 8;
            int b = row >> 11;
            int tok = row & (Nn - 1);
#pragma unroll
            for (int nf = 0; nf < 4; nf++) {
                int col = bn + wn + nf * 8 + (l & 3) * 2;   // even
                float y0 = acc[mf][nf][half * 2 + 0];
                float y1 = acc[mf][nf][half * 2 + 1];
                int region = col >> 10;
                int cc = col & 1023;
                int h = cc >> 6;
                int dd = cc & 63;
                int bh = b * Hh + h;
                uint16_t h0, l0, h1, l1;
                if (region == 2) {
                    size_t vb = ((size_t)bh * Dd + dd) * Nn + tok;
                    fsplit(y0, h0, l0);
                    fsplit(y1, h1, l1);
                    g_vh[vb]      = h0;  g_vl[vb]      = l0;
                    g_vh[vb + Nn] = h1;  g_vl[vb + Nn] = l1;
                } else {
                    size_t base = ((size_t)bh * Nn + tok) * Dd;
                    int i1 = dd >> 1;
                    float cs = g_cos[tok * 32 + i1];
                    float sn = g_sin[tok * 32 + i1];
                    float r0 = y0 * cs - y1 * sn;
                    float r1 = y0 * sn + y1 * cs;
                    uint16_t* dh = region ? g_kh : g_qh;
                    uint16_t* dl = region ? g_kl : g_ql;
                    fsplit(r0, h0, l0);
                    fsplit(r1, h1, l1);
                    dh[base + i1]      = h0; dl[base + i1]      = l0;
                    dh[base + i1 + 32] = h1; dl[base + i1 + 32] = l1;
                }
            }
        }
    }
}

// ---------------- GEMM3: out = O @ WoutT + bias ------------------------------
__global__ __launch_bounds__(256) void out_mma_gemm(const float* __restrict__ bias,
                                                    float* __restrict__ out) {
    extern __shared__ char sm[];
    int bm = blockIdx.y * 128, bn = blockIdx.x * 128;
    float acc[4][4][4];
    gemm_core5(g_oh, g_ol, g_woh, g_wol, bm, bn, sm, acc);

    int tid = threadIdx.x, l = tid & 31, w = tid >> 5;
    int wm = (w >> 2) * 64, wn = (w & 3) * 32;

#pragma unroll
    for (int mf = 0; mf < 4; mf++) {
#pragma unroll
        for (int half = 0; half < 2; half++) {
            int row = bm + wm + mf * 16 + (l >> 2) + half * 8;
#pragma unroll
            for (int nf = 0; nf < 4; nf++) {
                int col = bn + wn + nf * 8 + (l & 3) * 2;
                float y0 = acc[mf][nf][half * 2 + 0] + bias[col];
                float y1 = acc[mf][nf][half * 2 + 1] + bias[col + 1];
                *(float2*)(out + (size_t)row * Cc + col) = make_float2(y0, y1);
            }
        }
    }
}

// ========== Flash attention: paired q-tiles (uniform work), 2-stage cp.async =
// Each CTA processes q-tile blockIdx.x and q-tile (NQB-1 - blockIdx.x):
// work = (2a+2)+(2(15-a)+2) = 34 tile-units for every CTA -> single balanced wave.
#define AP 72
#define AT_SMEM 110592

__global__ __launch_bounds__(256, 2) void flash_mma_kernel() {
    extern __shared__ char sm[];
    uint16_t* sQh = (uint16_t*)sm;
    uint16_t* sQl = (uint16_t*)(sm + 18432);
    uint32_t sb0 = smem_u32(sm);

    int tid = threadIdx.x, l = tid & 31, w = tid >> 5;
    int wm = w * 16;
    int bh = blockIdx.y;
    int b = bh >> 4, h = bh & 15;

    const uint16_t* Kph = g_kh + (size_t)bh * Nn * Dd;
    const uint16_t* Kpl = g_kl + (size_t)bh * Nn * Dd;
    const uint16_t* Vph = g_vh + (size_t)bh * Dd * Nn;   // [d][pos]
    const uint16_t* Vpl = g_vl + (size_t)bh * Dd * Nn;

#pragma unroll 1
    for (int rep = 0; rep < 2; rep++) {
        int qb = rep == 0 ? (int)blockIdx.x : (NQB - 1 - (int)blockIdx.x);

        __syncthreads();   // guard smem reuse across reps

        // ---- Q: copy pre-split tile ----
        const uint16_t* Qh = g_qh + ((size_t)bh * Nn + qb * 128) * Dd;
        const uint16_t* Ql = g_ql + ((size_t)bh * Nn + qb * 128) * Dd;
#pragma unroll
        for (int i = 0; i < 4; i++) {
            int idx = tid + 256 * i;
            int r = idx >> 3, g = idx & 7;
            size_t off = (size_t)r * Dd + g * 8;
            *(uint4*)&sQh[r * AP + g * 8] = *(const uint4*)(Qh + off);
            *(uint4*)&sQl[r * AP + g * 8] = *(const uint4*)(Ql + off);
        }

        float O[8][4];
#pragma unroll
        for (int nf = 0; nf < 8; nf++)
#pragma unroll
            for (int i = 0; i < 4; i++) O[nf][i] = 0.0f;
        float mrow[2] = {-1e30f, -1e30f};
        float lsum[2] = {0.0f, 0.0f};

        auto issue_kv = [&](int t, int st) {
            uint32_t s0 = sb0 + 36864 + st * 36864;
#pragma unroll
            for (int i = 0; i < 2; i++) {
                int idx = tid + 256 * i;
                int r = idx >> 3, g = idx & 7;
                uint32_t d = s0 + r * 144 + g * 16;
                cpa16(d,          Kph + (size_t)(t * 64 + r) * Dd + g * 8);
                cpa16(d + 9216,   Kpl + (size_t)(t * 64 + r) * Dd + g * 8);
                cpa16(d + 18432,  Vph + (size_t)r * Nn + t * 64 + g * 8);
                cpa16(d + 27648,  Vpl + (size_t)r * Nn + t * 64 + g * 8);
            }
        };

        const int ntiles = 2 * qb + 2;
        issue_kv(0, 0); CP_COMMIT();

        for (int t = 0; t < ntiles; t++) {
            CP_WAIT0();
            __syncthreads();
            if (t + 1 < ntiles) { issue_kv(t + 1, (t + 1) & 1); CP_COMMIT(); }

            const char* s0 = sm + 36864 + (t & 1) * 36864;
            const uint16_t* sKh = (const uint16_t*)(s0);
            const uint16_t* sKl = (const uint16_t*)(s0 + 9216);
            const uint16_t* sVh = (const uint16_t*)(s0 + 18432);
            const uint16_t* sVl = (const uint16_t*)(s0 + 27648);

            // ---- S = Q K^T (bf16x3) ----
            float S[8][4];
#pragma unroll
            for (int nf = 0; nf < 8; nf++)
#pragma unroll
                for (int i = 0; i < 4; i++) S[nf][i] = 0.0f;

#pragma unroll
            for (int ks = 0; ks < 4; ks++) {
                int kc = ks * 16 + (l & 3) * 2;
                int r = wm + (l >> 2);
                uint32_t qh[4], ql[4];
                qh[0] = *(const uint32_t*)&sQh[(r    ) * AP + kc];
                qh[1] = *(const uint32_t*)&sQh[(r + 8) * AP + kc];
                qh[2] = *(const uint32_t*)&sQh[(r    ) * AP + kc + 8];
                qh[3] = *(const uint32_t*)&sQh[(r + 8) * AP + kc + 8];
                ql[0] = *(const uint32_t*)&sQl[(r    ) * AP + kc];
                ql[1] = *(const uint32_t*)&sQl[(r + 8) * AP + kc];
                ql[2] = *(const uint32_t*)&sQl[(r    ) * AP + kc + 8];
                ql[3] = *(const uint32_t*)&sQl[(r + 8) * AP + kc + 8];
#pragma unroll
                for (int nf = 0; nf < 8; nf++) {
                    int n = nf * 8 + (l >> 2);
                    uint32_t kh2[2], kl2[2];
                    kh2[0] = *(const uint32_t*)&sKh[n * AP + kc];
                    kh2[1] = *(const uint32_t*)&sKh[n * AP + kc + 8];
                    kl2[0] = *(const uint32_t*)&sKl[n * AP + kc];
                    kl2[1] = *(const uint32_t*)&sKl[n * AP + kc + 8];
                    mma_bf16(S[nf], qh, kh2);
                    mma_bf16(S[nf], ql, kh2);
                    mma_bf16(S[nf], qh, kl2);
                }
            }

            // ---- scale + causal mask ----
            bool domask = (t >= 2 * qb);
#pragma unroll
            for (int nf = 0; nf < 8; nf++)
#pragma unroll
                for (int idx = 0; idx < 4; idx++) {
                    float v = S[nf][idx] * SL2E;
                    if (domask) {
                        int h2 = idx >> 1, ci = idx & 1;
                        int qg = qb * 128 + wm + (l >> 2) + h2 * 8;
                        int kg = t * 64 + nf * 8 + (l & 3) * 2 + ci;
                        if (kg > qg) v = -1e30f;
                    }
                    S[nf][idx] = v;
                }

            // ---- online softmax ----
#pragma unroll
            for (int h2 = 0; h2 < 2; h2++) {
                float mx = -1e30f;
#pragma unroll
                for (int nf = 0; nf < 8; nf++)
                    mx = fmaxf(mx, fmaxf(S[nf][h2*2], S[nf][h2*2+1]));
                mx = fmaxf(mx, __shfl_xor_sync(0xffffffffu, mx, 1));
                mx = fmaxf(mx, __shfl_xor_sync(0xffffffffu, mx, 2));
                float mnew = fmaxf(mrow[h2], mx);
                float scl = ex2(mrow[h2] - mnew);
                float sum = 0.0f;
#pragma unroll
                for (int nf = 0; nf < 8; nf++) {
                    float p0 = ex2(S[nf][h2*2]   - mnew);
                    float p1 = ex2(S[nf][h2*2+1] - mnew);
                    S[nf][h2*2]   = p0;
                    S[nf][h2*2+1] = p1;
                    sum += p0 + p1;
                }
                sum += __shfl_xor_sync(0xffffffffu, sum, 1);
                sum += __shfl_xor_sync(0xffffffffu, sum, 2);
                lsum[h2] = lsum[h2] * scl + sum;
                mrow[h2] = mnew;
#pragma unroll
                for (int nf = 0; nf < 8; nf++) {
                    O[nf][h2*2]   *= scl;
                    O[nf][h2*2+1] *= scl;
                }
            }

            // ---- O += P V ----
#pragma unroll
            for (int ks = 0; ks < 4; ks++) {
                uint32_t ph[4], pl[4];
#pragma unroll
                for (int half = 0; half < 2; half++) {
#pragma unroll
                    for (int rr = 0; rr < 2; rr++) {
                        float v0 = S[2*ks + half][rr*2];
                        float v1 = S[2*ks + half][rr*2 + 1];
                        uint16_t a0, b0, a1, b1;
                        fsplit(v0, a0, b0);
                        fsplit(v1, a1, b1);
                        ph[half*2 + rr] = (uint32_t)a0 | ((uint32_t)a1 << 16);
                        pl[half*2 + rr] = (uint32_t)b0 | ((uint32_t)b1 << 16);
                    }
                }
                int kc = ks * 16 + (l & 3) * 2;
#pragma unroll
                for (int nf = 0; nf < 8; nf++) {
                    int n = nf * 8 + (l >> 2);
                    uint32_t vh2[2], vl2[2];
                    vh2[0] = *(const uint32_t*)&sVh[n * AP + kc];
                    vh2[1] = *(const uint32_t*)&sVh[n * AP + kc + 8];
                    vl2[0] = *(const uint32_t*)&sVl[n * AP + kc];
                    vl2[1] = *(const uint32_t*)&sVl[n * AP + kc + 8];
                    mma_bf16(O[nf], ph, vh2);
                    mma_bf16(O[nf], pl, vh2);
                    mma_bf16(O[nf], ph, vl2);
                }
            }
        }

        // ---- finalize: O /= l, store bf16 h/l to g_oh/g_ol [m][c] ----
        float inv[2] = {1.0f / lsum[0], 1.0f / lsum[1]};
#pragma unroll
        for (int nf = 0; nf < 8; nf++)
#pragma unroll
            for (int idx = 0; idx < 4; idx++) {
                int h2 = idx >> 1, ci = idx & 1;
                int q = qb * 128 + wm + (l >> 2) + h2 * 8;
                int col = h * 64 + nf * 8 + (l & 3) * 2 + ci;
                size_t o = (size_t)(b * Nn + q) * Cc + col;
                uint16_t hh, ll;
                fsplit(O[nf][idx] * inv[h2], hh, ll);
                g_oh[o] = hh;
                g_ol[o] = ll;
            }
    }
}

// ---------------- launch -----------------------------------------------------
extern "C" void kernel_launch(void* const* d_in, const int* in_sizes, int n_in,
                              void* d_out, int out_size)
{
    (void)in_sizes; (void)n_in; (void)out_size;
    const float* x    = (const float*)d_in[0];
    const float* Wqkv = (const float*)d_in[1];
    const float* Wout = (const float*)d_in[2];
    const float* bout = (const float*)d_in[3];
    float* out = (float*)d_out;

    cudaFuncSetAttribute(qkv_mma_gemm, cudaFuncAttributeMaxDynamicSharedMemorySize, GEMM_SMEM);
    cudaFuncSetAttribute(out_mma_gemm, cudaFuncAttributeMaxDynamicSharedMemorySize, GEMM_SMEM);
    cudaFuncSetAttribute(flash_mma_kernel, cudaFuncAttributeMaxDynamicSharedMemorySize, AT_SMEM);

    rope_init_kernel<<<(Nn * 32 + 255) / 256, 256>>>();
    split_x_kernel<<<(Mtot * Cc / 4) / 256, 256>>>(x);
    transpose_split_kernel<<<dim3(K3 / 32, Cc / 32), dim3(32, 8)>>>(Wqkv, Cc, K3, 0);
    transpose_split_kernel<<<dim3(Cc / 32, Cc / 32), dim3(32, 8)>>>(Wout, Cc, Cc, 1);
    qkv_mma_gemm<<<dim3(K3 / 128, Mtot / 128), 256, GEMM_SMEM>>>();
    flash_mma_kernel<<<dim3(NQB / 2, Bb * Hh), 256, AT_SMEM>>>();
    out_mma_gemm<<<dim3(Cc / 128, Mtot / 128), 256, GEMM_SMEM>>>(bout, out);
}

// round 16
// speedup vs baseline: 1.9457x; 1.4753x over previous
#include <cuda_runtime.h>
#include <cuda_fp16.h>
#include <math.h>
#include <stdint.h>

#define Bb 2
#define Nn 2048
#define Cc 1024
#define Hh 16
#define Dd 64
#define Mtot (Bb*Nn)     /* 4096 */
#define K3  (3*Cc)       /* 3072 */
#define NQB 16           /* q-tiles of 128 */
#define SL2E 0.1803368801111244f   /* 0.125 * log2(e) */

// ---------------- scratch ----------------------------------------------------
__device__ __align__(16) uint16_t g_wqh[(size_t)K3*Cc];                 // WqkvT [n][k] fp16
__device__ __align__(16) uint16_t g_woh[(size_t)Cc*Cc];                 // WoutT [n][k] fp16
__device__ __align__(16) uint16_t g_xh[(size_t)Mtot*Cc], g_xl[(size_t)Mtot*Cc]; // x h/l
__device__ __align__(16) uint16_t g_qh[(size_t)Bb*Hh*Nn*Dd], g_ql[(size_t)Bb*Hh*Nn*Dd]; // [bh][pos][d]
__device__ __align__(16) uint16_t g_kh[(size_t)Bb*Hh*Nn*Dd];            // [bh][pos][d]
__device__ __align__(16) uint16_t g_vh[(size_t)Bb*Hh*Nn*Dd];            // [bh][d][pos]
__device__ __align__(16) uint16_t g_oh[(size_t)Mtot*Cc], g_ol[(size_t)Mtot*Cc]; // attn out h/l
__device__ float g_cos[Nn*32], g_sin[Nn*32];

// ---------------- helpers ----------------------------------------------------
__device__ __forceinline__ uint32_t smem_u32(const void* p) {
    uint32_t a;
    asm("{ .reg .u64 t; cvta.to.shared.u64 t, %1; cvt.u32.u64 %0, t; }" : "=r"(a) : "l"(p));
    return a;
}
__device__ __forceinline__ void cpa16(uint32_t s, const void* g) {
    asm volatile("cp.async.cg.shared.global [%0], [%1], 16;" :: "r"(s), "l"(g) : "memory");
}
#define CP_COMMIT() asm volatile("cp.async.commit_group;" ::: "memory")
#define CP_WAIT0()  asm volatile("cp.async.wait_group 0;" ::: "memory")

__device__ __forceinline__ void ldsm4(uint32_t* r, uint32_t addr) {
    asm volatile("ldmatrix.sync.aligned.m8n8.x4.shared.b16 {%0,%1,%2,%3}, [%4];"
        : "=r"(r[0]), "=r"(r[1]), "=r"(r[2]), "=r"(r[3]) : "r"(addr));
}
__device__ __forceinline__ void mma_f16(float* c, const uint32_t* a, const uint32_t* b) {
    asm volatile("mma.sync.aligned.m16n8k16.row.col.f32.f16.f16.f32 "
        "{%0,%1,%2,%3}, {%4,%5,%6,%7}, {%8,%9}, {%0,%1,%2,%3};"
        : "+f"(c[0]), "+f"(c[1]), "+f"(c[2]), "+f"(c[3])
        : "r"(a[0]), "r"(a[1]), "r"(a[2]), "r"(a[3]), "r"(b[0]), "r"(b[1]));
}
__device__ __forceinline__ void hsplit(float x, uint16_t& h, uint16_t& lo) {
    __half hb = __float2half_rn(x);
    float r = x - __half2float(hb);
    __half lb = __float2half_rn(r);
    h  = *(uint16_t*)&hb;
    lo = *(uint16_t*)&lb;
}
__device__ __forceinline__ uint16_t h16(float x) {
    __half hb = __float2half_rn(x);
    return *(uint16_t*)&hb;
}
__device__ __forceinline__ float ex2(float x) {
    float y;
    asm("ex2.approx.ftz.f32 %0, %1;" : "=f"(y) : "f"(x));
    return y;
}

// ---------------- init kernels -----------------------------------------------
__global__ void rope_init_kernel() {
    int idx = blockIdx.x * blockDim.x + threadIdx.x;
    if (idx >= Nn * 32) return;
    int n = idx >> 5, i = idx & 31;
    float invf = powf(10000.0f, -(float)i / 32.0f);
    float f = (float)n * invf;
    g_cos[idx] = cosf(f);
    g_sin[idx] = sinf(f);
}

__global__ __launch_bounds__(256) void split_x_kernel(const float* __restrict__ xp) {
    size_t i = ((size_t)blockIdx.x * 256 + threadIdx.x) * 4;
    float4 v = *(const float4*)(xp + i);
    uint16_t h0,l0,h1,l1,h2,l2,h3,l3;
    hsplit(v.x, h0, l0); hsplit(v.y, h1, l1);
    hsplit(v.z, h2, l2); hsplit(v.w, h3, l3);
    *(uint2*)(g_xh + i) = make_uint2((uint32_t)h0 | ((uint32_t)h1 << 16),
                                     (uint32_t)h2 | ((uint32_t)h3 << 16));
    *(uint2*)(g_xl + i) = make_uint2((uint32_t)l0 | ((uint32_t)l1 << 16),
                                     (uint32_t)l2 | ((uint32_t)l3 << 16));
}

// W [R][C] -> T [C][R] (fp16 hi only), device-selected destinations
// (GB300/ATS trap: never pass __device__ symbols from host).
__global__ void transpose_split_kernel(const float* __restrict__ W,
                                       int R, int C, int which) {
    uint16_t* __restrict__ Th = which ? g_woh : g_wqh;
    __shared__ float tile[32][33];
    int bx = blockIdx.x * 32, by = blockIdx.y * 32;
    int tx = threadIdx.x, ty = threadIdx.y;
#pragma unroll
    for (int i = 0; i < 4; i++)
        tile[ty + 8*i][tx] = W[(size_t)(by + ty + 8*i) * C + bx + tx];
    __syncthreads();
#pragma unroll
    for (int i = 0; i < 4; i++) {
        size_t o = (size_t)(bx + ty + 8*i) * R + by + tx;
        Th[o] = h16(tile[tx][ty + 8*i]);
    }
}

// == fp16x2 GEMM core: BK=64, 2-stage cp.async, 1 sync/iter, ldmatrix =========
// Stage (55296 B): Ah 0 | Al 18432 | Bh 36864; row stride 144 B (GP2=72 u16).
#define GEMM_SMEM 110592
#define GP2 72

__device__ __forceinline__ void gemm_core6(
    const uint16_t* __restrict__ Ah, const uint16_t* __restrict__ Al,
    const uint16_t* __restrict__ Bh,
    int bm, int bn, char* sm, float acc[4][4][4])
{
    int tid = threadIdx.x, l = tid & 31, w = tid >> 5;
    int wm = (w >> 2) * 64, wn = (w & 3) * 32;
    uint32_t sb0 = smem_u32(sm);

#pragma unroll
    for (int mf = 0; mf < 4; mf++)
#pragma unroll
        for (int nf = 0; nf < 4; nf++)
#pragma unroll
            for (int i = 0; i < 4; i++) acc[mf][nf][i] = 0.0f;

    auto issue = [&](int st, int kt) {
        uint32_t s0 = sb0 + st * 55296;
#pragma unroll
        for (int i = 0; i < 4; i++) {
            int ch = tid + 256 * i;
            int r = ch >> 3, g = ch & 7;
            uint32_t d = s0 + r * 144 + g * 16;
            size_t offa = (size_t)(bm + r) * Cc + kt * 64 + g * 8;
            size_t offb = (size_t)(bn + r) * Cc + kt * 64 + g * 8;
            cpa16(d,          Ah + offa);
            cpa16(d + 18432,  Al + offa);
            cpa16(d + 36864,  Bh + offb);
        }
    };

    issue(0, 0); CP_COMMIT();
    for (int kt = 0; kt < 16; kt++) {
        CP_WAIT0();
        __syncthreads();
        if (kt + 1 < 16) { issue((kt + 1) & 1, kt + 1); CP_COMMIT(); }

        uint32_t sb = sb0 + (kt & 1) * 55296;
#pragma unroll
        for (int ks = 0; ks < 4; ks++) {
            int k0 = ks * 16;
            uint32_t ah[4][4], al[4][4];
            uint32_t arow = (uint32_t)(wm + (l & 15));
            uint32_t acol = (uint32_t)(k0 + (l >> 4) * 8);
#pragma unroll
            for (int mf = 0; mf < 4; mf++) {
                uint32_t off = ((arow + mf * 16) * GP2 + acol) * 2;
                ldsm4(ah[mf], sb + off);
                ldsm4(al[mf], sb + 18432 + off);
            }
            uint32_t bh2[4][2];
            uint32_t brow = (uint32_t)(wn + (l >> 4) * 8 + (l & 7));
            uint32_t bcol = (uint32_t)(k0 + ((l >> 3) & 1) * 8);
#pragma unroll
            for (int p = 0; p < 2; p++) {
                uint32_t off = ((brow + p * 16) * GP2 + bcol) * 2;
                uint32_t tb[4];
                ldsm4(tb, sb + 36864 + off);
                bh2[2*p][0] = tb[0]; bh2[2*p][1] = tb[1];
                bh2[2*p+1][0] = tb[2]; bh2[2*p+1][1] = tb[3];
            }
#pragma unroll
            for (int nf = 0; nf < 4; nf++)
#pragma unroll
                for (int mf = 0; mf < 4; mf++) {
                    mma_f16(acc[mf][nf], ah[mf], bh2[nf]);
                    mma_f16(acc[mf][nf], al[mf], bh2[nf]);
                }
        }
    }
}

// ---------------- GEMM1: qkv + RoPE epilogue, writes pre-split Q/K/V ---------
__global__ __launch_bounds__(256) void qkv_mma_gemm(void) {
    extern __shared__ char sm[];
    int bm = blockIdx.y * 128, bn = blockIdx.x * 128;
    float acc[4][4][4];
    gemm_core6(g_xh, g_xl, g_wqh, bm, bn, sm, acc);

    int tid = threadIdx.x, l = tid & 31, w = tid >> 5;
    int wm = (w >> 2) * 64, wn = (w & 3) * 32;

#pragma unroll
    for (int mf = 0; mf < 4; mf++) {
#pragma unroll
        for (int half = 0; half < 2; half++) {
            int row = bm + wm + mf * 16 + (l >> 2) + half * 8;
            int b = row >> 11;
            int tok = row & (Nn - 1);
#pragma unroll
            for (int nf = 0; nf < 4; nf++) {
                int col = bn + wn + nf * 8 + (l & 3) * 2;   // even
                float y0 = acc[mf][nf][half * 2 + 0];
                float y1 = acc[mf][nf][half * 2 + 1];
                int region = col >> 10;
                int cc = col & 1023;
                int h = cc >> 6;
                int dd = cc & 63;
                int bh = b * Hh + h;
                if (region == 2) {
                    // V transposed [bh][d][pos], fp16 hi only
                    size_t vb = ((size_t)bh * Dd + dd) * Nn + tok;
                    g_vh[vb]      = h16(y0);
                    g_vh[vb + Nn] = h16(y1);
                } else {
                    size_t base = ((size_t)bh * Nn + tok) * Dd;
                    int i1 = dd >> 1;
                    float cs = g_cos[tok * 32 + i1];
                    float sn = g_sin[tok * 32 + i1];
                    float r0 = y0 * cs - y1 * sn;
                    float r1 = y0 * sn + y1 * cs;
                    if (region) {                 // K: hi only
                        g_kh[base + i1]      = h16(r0);
                        g_kh[base + i1 + 32] = h16(r1);
                    } else {                      // Q: hi + lo
                        uint16_t h0, l0, h1, l1;
                        hsplit(r0, h0, l0);
                        hsplit(r1, h1, l1);
                        g_qh[base + i1]      = h0; g_ql[base + i1]      = l0;
                        g_qh[base + i1 + 32] = h1; g_ql[base + i1 + 32] = l1;
                    }
                }
            }
        }
    }
}

// ---------------- GEMM3: out = O @ WoutT + bias ------------------------------
__global__ __launch_bounds__(256) void out_mma_gemm(const float* __restrict__ bias,
                                                    float* __restrict__ out) {
    extern __shared__ char sm[];
    int bm = blockIdx.y * 128, bn = blockIdx.x * 128;
    float acc[4][4][4];
    gemm_core6(g_oh, g_ol, g_woh, bm, bn, sm, acc);

    int tid = threadIdx.x, l = tid & 31, w = tid >> 5;
    int wm = (w >> 2) * 64, wn = (w & 3) * 32;

#pragma unroll
    for (int mf = 0; mf < 4; mf++) {
#pragma unroll
        for (int half = 0; half < 2; half++) {
            int row = bm + wm + mf * 16 + (l >> 2) + half * 8;
#pragma unroll
            for (int nf = 0; nf < 4; nf++) {
                int col = bn + wn + nf * 8 + (l & 3) * 2;
                float y0 = acc[mf][nf][half * 2 + 0] + bias[col];
                float y1 = acc[mf][nf][half * 2 + 1] + bias[col + 1];
                *(float2*)(out + (size_t)row * Cc + col) = make_float2(y0, y1);
            }
        }
    }
}

// ========== Flash attention: fp16x2, paired q-tiles, 2-stage cp.async ========
// Smem: Qh 0 (18432) Ql 18432 | KV stage s at 36864 + s*18432: Kh +0, Vh +9216.
#define AP 72
#define AT_SMEM 73728

__global__ __launch_bounds__(256, 2) void flash_mma_kernel() {
    extern __shared__ char sm[];
    uint16_t* sQh = (uint16_t*)sm;
    uint16_t* sQl = (uint16_t*)(sm + 18432);
    uint32_t sb0 = smem_u32(sm);

    int tid = threadIdx.x, l = tid & 31, w = tid >> 5;
    int wm = w * 16;
    int bh = blockIdx.y;
    int b = bh >> 4, h = bh & 15;

    const uint16_t* Kph = g_kh + (size_t)bh * Nn * Dd;
    const uint16_t* Vph = g_vh + (size_t)bh * Dd * Nn;   // [d][pos]

#pragma unroll 1
    for (int rep = 0; rep < 2; rep++) {
        int qb = rep == 0 ? (int)blockIdx.x : (NQB - 1 - (int)blockIdx.x);

        __syncthreads();   // guard smem reuse across reps

        // ---- Q: copy pre-split tile ----
        const uint16_t* Qh = g_qh + ((size_t)bh * Nn + qb * 128) * Dd;
        const uint16_t* Ql = g_ql + ((size_t)bh * Nn + qb * 128) * Dd;
#pragma unroll
        for (int i = 0; i < 4; i++) {
            int idx = tid + 256 * i;
            int r = idx >> 3, g = idx & 7;
            size_t off = (size_t)r * Dd + g * 8;
            *(uint4*)&sQh[r * AP + g * 8] = *(const uint4*)(Qh + off);
            *(uint4*)&sQl[r * AP + g * 8] = *(const uint4*)(Ql + off);
        }

        float O[8][4];
#pragma unroll
        for (int nf = 0; nf < 8; nf++)
#pragma unroll
            for (int i = 0; i < 4; i++) O[nf][i] = 0.0f;
        float mrow[2] = {-1e30f, -1e30f};
        float lsum[2] = {0.0f, 0.0f};

        auto issue_kv = [&](int t, int st) {
            uint32_t s0 = sb0 + 36864 + st * 18432;
#pragma unroll
            for (int i = 0; i < 2; i++) {
                int idx = tid + 256 * i;
                int r = idx >> 3, g = idx & 7;
                uint32_t d = s0 + r * 144 + g * 16;
                cpa16(d,         Kph + (size_t)(t * 64 + r) * Dd + g * 8);
                cpa16(d + 9216,  Vph + (size_t)r * Nn + t * 64 + g * 8);
            }
        };

        const int ntiles = 2 * qb + 2;
        issue_kv(0, 0); CP_COMMIT();

        for (int t = 0; t < ntiles; t++) {
            CP_WAIT0();
            __syncthreads();
            if (t + 1 < ntiles) { issue_kv(t + 1, (t + 1) & 1); CP_COMMIT(); }

            const char* s0 = sm + 36864 + (t & 1) * 18432;
            const uint16_t* sKh = (const uint16_t*)(s0);
            const uint16_t* sVh = (const uint16_t*)(s0 + 9216);

            // ---- S = Q K^T (fp16x2: qh+ql fully correct Q, K hi) ----
            float S[8][4];
#pragma unroll
            for (int nf = 0; nf < 8; nf++)
#pragma unroll
                for (int i = 0; i < 4; i++) S[nf][i] = 0.0f;

#pragma unroll
            for (int ks = 0; ks < 4; ks++) {
                int kc = ks * 16 + (l & 3) * 2;
                int r = wm + (l >> 2);
                uint32_t qh[4], ql[4];
                qh[0] = *(const uint32_t*)&sQh[(r    ) * AP + kc];
                qh[1] = *(const uint32_t*)&sQh[(r + 8) * AP + kc];
                qh[2] = *(const uint32_t*)&sQh[(r    ) * AP + kc + 8];
                qh[3] = *(const uint32_t*)&sQh[(r + 8) * AP + kc + 8];
                ql[0] = *(const uint32_t*)&sQl[(r    ) * AP + kc];
                ql[1] = *(const uint32_t*)&sQl[(r + 8) * AP + kc];
                ql[2] = *(const uint32_t*)&sQl[(r    ) * AP + kc + 8];
                ql[3] = *(const uint32_t*)&sQl[(r + 8) * AP + kc + 8];
#pragma unroll
                for (int nf = 0; nf < 8; nf++) {
                    int n = nf * 8 + (l >> 2);
                    uint32_t kh2[2];
                    kh2[0] = *(const uint32_t*)&sKh[n * AP + kc];
                    kh2[1] = *(const uint32_t*)&sKh[n * AP + kc + 8];
                    mma_f16(S[nf], qh, kh2);
                    mma_f16(S[nf], ql, kh2);
                }
            }

            // ---- scale + causal mask ----
            bool domask = (t >= 2 * qb);
#pragma unroll
            for (int nf = 0; nf < 8; nf++)
#pragma unroll
                for (int idx = 0; idx < 4; idx++) {
                    float v = S[nf][idx] * SL2E;
                    if (domask) {
                        int h2 = idx >> 1, ci = idx & 1;
                        int qg = qb * 128 + wm + (l >> 2) + h2 * 8;
                        int kg = t * 64 + nf * 8 + (l & 3) * 2 + ci;
                        if (kg > qg) v = -1e30f;
                    }
                    S[nf][idx] = v;
                }

            // ---- online softmax ----
#pragma unroll
            for (int h2 = 0; h2 < 2; h2++) {
                float mx = -1e30f;
#pragma unroll
                for (int nf = 0; nf < 8; nf++)
                    mx = fmaxf(mx, fmaxf(S[nf][h2*2], S[nf][h2*2+1]));
                mx = fmaxf(mx, __shfl_xor_sync(0xffffffffu, mx, 1));
                mx = fmaxf(mx, __shfl_xor_sync(0xffffffffu, mx, 2));
                float mnew = fmaxf(mrow[h2], mx);
                float scl = ex2(mrow[h2] - mnew);
                float sum = 0.0f;
#pragma unroll
                for (int nf = 0; nf < 8; nf++) {
                    float p0 = ex2(S[nf][h2*2]   - mnew);
                    float p1 = ex2(S[nf][h2*2+1] - mnew);
                    S[nf][h2*2]   = p0;
                    S[nf][h2*2+1] = p1;
                    sum += p0 + p1;
                }
                sum += __shfl_xor_sync(0xffffffffu, sum, 1);
                sum += __shfl_xor_sync(0xffffffffu, sum, 2);
                lsum[h2] = lsum[h2] * scl + sum;
                mrow[h2] = mnew;
#pragma unroll
                for (int nf = 0; nf < 8; nf++) {
                    O[nf][h2*2]   *= scl;
                    O[nf][h2*2+1] *= scl;
                }
            }

            // ---- O += P V  (P fully corrected: ph+pl; V hi) ----
#pragma unroll
            for (int ks = 0; ks < 4; ks++) {
                uint32_t ph[4], pl[4];
#pragma unroll
                for (int half = 0; half < 2; half++) {
#pragma unroll
                    for (int rr = 0; rr < 2; rr++) {
                        float v0 = S[2*ks + half][rr*2];
                        float v1 = S[2*ks + half][rr*2 + 1];
                        uint16_t a0, b0, a1, b1;
                        hsplit(v0, a0, b0);
                        hsplit(v1, a1, b1);
                        ph[half*2 + rr] = (uint32_t)a0 | ((uint32_t)a1 << 16);
                        pl[half*2 + rr] = (uint32_t)b0 | ((uint32_t)b1 << 16);
                    }
                }
                int kc = ks * 16 + (l & 3) * 2;
#pragma unroll
                for (int nf = 0; nf < 8; nf++) {
                    int n = nf * 8 + (l >> 2);
                    uint32_t vh2[2];
                    vh2[0] = *(const uint32_t*)&sVh[n * AP + kc];
                    vh2[1] = *(const uint32_t*)&sVh[n * AP + kc + 8];
                    mma_f16(O[nf], ph, vh2);
                    mma_f16(O[nf], pl, vh2);
                }
            }
        }

        // ---- finalize: O /= l, store fp16 h/l to g_oh/g_ol [m][c] ----
        float inv[2] = {1.0f / lsum[0], 1.0f / lsum[1]};
#pragma unroll
        for (int nf = 0; nf < 8; nf++)
#pragma unroll
            for (int idx = 0; idx < 4; idx++) {
                int h2 = idx >> 1, ci = idx & 1;
                int q = qb * 128 + wm + (l >> 2) + h2 * 8;
                int col = h * 64 + nf * 8 + (l & 3) * 2 + ci;
                size_t o = (size_t)(b * Nn + q) * Cc + col;
                uint16_t hh, ll;
                hsplit(O[nf][idx] * inv[h2], hh, ll);
                g_oh[o] = hh;
                g_ol[o] = ll;
            }
    }
}

// ---------------- launch -----------------------------------------------------
extern "C" void kernel_launch(void* const* d_in, const int* in_sizes, int n_in,
                              void* d_out, int out_size)
{
    (void)in_sizes; (void)n_in; (void)out_size;
    const float* x    = (const float*)d_in[0];
    const float* Wqkv = (const float*)d_in[1];
    const float* Wout = (const float*)d_in[2];
    const float* bout = (const float*)d_in[3];
    float* out = (float*)d_out;

    cudaFuncSetAttribute(qkv_mma_gemm, cudaFuncAttributeMaxDynamicSharedMemorySize, GEMM_SMEM);
    cudaFuncSetAttribute(out_mma_gemm, cudaFuncAttributeMaxDynamicSharedMemorySize, GEMM_SMEM);
    cudaFuncSetAttribute(flash_mma_kernel, cudaFuncAttributeMaxDynamicSharedMemorySize, AT_SMEM);

    rope_init_kernel<<<(Nn * 32 + 255) / 256, 256>>>();
    split_x_kernel<<<(Mtot * Cc / 4) / 256, 256>>>(x);
    transpose_split_kernel<<<dim3(K3 / 32, Cc / 32), dim3(32, 8)>>>(Wqkv, Cc, K3, 0);
    transpose_split_kernel<<<dim3(Cc / 32, Cc / 32), dim3(32, 8)>>>(Wout, Cc, Cc, 1);
    qkv_mma_gemm<<<dim3(K3 / 128, Mtot / 128), 256, GEMM_SMEM>>>();
    flash_mma_kernel<<<dim3(NQB / 2, Bb * Hh), 256, AT_SMEM>>>();
    out_mma_gemm<<<dim3(Cc / 128, Mtot / 128), 256, GEMM_SMEM>>>(bout, out);
}